// round 15
// baseline (speedup 1.0000x reference)
#include <cuda_runtime.h>
#include <cuda.h>
#include <cuda_fp16.h>
#include <cstdint>

constexpr int B_ROWS = 8192;
constexpr int DIM    = 1024;
constexpr int TILE_M = 128;
constexpr int KT     = 64;
constexpr int NCHUNKS = DIM / KT;          // 16

constexpr uint32_t IDESC256 = (1u << 4) | ((256u / 8u) << 17) | ((128u / 16u) << 24);

constexpr uint32_t STAGE_A = 48 * 1024;    // gemm_a: A 16K + B(256 rows) 32K
constexpr uint32_t STAGE_B = 64 * 1024;    // gemm_b: A0 16K + A1 16K + B(256 rows) 32K
constexpr uint32_t HDR_BYTES = 1024;
constexpr uint32_t SMEM_DYN  = 1024 + HDR_BYTES + 192 * 1024;   // covers 4x48K and 3x64K

constexpr size_t CSTR = (size_t)B_ROWS * DIM;

__device__ __half g_P16[(size_t)B_ROWS * DIM];
__device__ __half g_C16[(size_t)4 * B_ROWS * DIM];
__device__ __half g_W16[(size_t)3 * DIM * DIM];
__device__ __half g_WPH[(size_t)B_ROWS * DIM];
__device__ float  g_WPO[(size_t)B_ROWS * DIM];

#if defined(__CUDA_ARCH__) && (defined(__CUDA_ARCH_FEAT_SM103_ALL) || defined(__CUDA_ARCH_FEAT_SM100_ALL) || defined(__CUDA_ARCH_FAMILY_SPECIFIC__))
#define USE_TC 1
#else
#define USE_TC 0
#endif

__device__ __forceinline__ uint32_t smem_u32(const void* p) {
    uint32_t a;
    asm("{ .reg .u64 t; cvta.to.shared.u64 t, %1; cvt.u32.u64 %0, t; }" : "=r"(a) : "l"(p));
    return a;
}
__device__ __forceinline__ uint32_t swz(uint32_t off) { return off ^ ((off >> 3) & 0x70); }

static constexpr uint64_t SMEM_DESC_BASE_SW128 =
    (uint64_t(2) << 61) | (uint64_t(1) << 46) | (uint64_t(64) << 32) | (uint64_t(1) << 16);
#define MAKE_SMEM_DESC(base_addr) \
    (SMEM_DESC_BASE_SW128 | ((uint64_t)((base_addr) >> 4) & 0x3FFF))

#define CP_ASYNC16(dst, src) \
    asm volatile("cp.async.cg.shared.global [%0], [%1], 16;" :: "r"(dst), "l"(src))

#define PREFETCH_L2(p) \
    asm volatile("prefetch.global.L2 [%0];" :: "l"(p))

#define MBARRIER_INIT(addr, count) \
    asm volatile("mbarrier.init.shared.b64 [%0], %1;" :: "r"((uint32_t)(addr)), "r"((uint32_t)(count)) : "memory")

#define MBARRIER_EXPECT_TX(addr, bytes) \
    asm volatile("mbarrier.arrive.expect_tx.shared.b64 _, [%0], %1;" \
                 :: "r"((uint32_t)(addr)), "r"((uint32_t)(bytes)) : "memory")

#define TMA_LOAD_2D(smem_addr, map_ptr, cx, cy, mbar) \
    asm volatile("cp.async.bulk.tensor.2d.shared::cta.global.tile.mbarrier::complete_tx::bytes " \
                 "[%0], [%1, {%2, %3}], [%4];" \
                 :: "r"((uint32_t)(smem_addr)), "l"(map_ptr), "r"((int)(cx)), "r"((int)(cy)), \
                    "r"((uint32_t)(mbar)) : "memory")

#define MBARRIER_WAIT_PARITY(mbar_smem_addr, phase_parity) do { \
    uint32_t _mbar = (uint32_t)(mbar_smem_addr); \
    uint32_t _parity = (uint32_t)(phase_parity); \
    uint32_t _done; \
    asm volatile( \
        "{\n\t.reg .pred p;\n\t" \
        "mbarrier.try_wait.parity.acquire.cta.shared::cta.b64 p, [%1], %2;\n\t" \
        "selp.b32 %0, 1, 0, p;\n\t}" \
        : "=r"(_done) : "r"(_mbar), "r"(_parity) : "memory"); \
    if (!_done) { \
        asm volatile( \
            "{\n\t.reg .pred P1;\n\t" \
            "WAIT_LOOP_%=:\n\t" \
            "mbarrier.try_wait.parity.acquire.cta.shared::cta.b64 P1, [%0], %1, 0x989680;\n\t" \
            "@P1 bra.uni WAIT_DONE_%=;\n\t" \
            "bra.uni WAIT_LOOP_%=;\n\t" \
            "WAIT_DONE_%=:\n\t}" \
            :: "r"(_mbar), "r"(_parity) : "memory"); \
    } \
} while (0)

#define TCGEN05_ALLOC(smem_result_addr, nCols) \
    asm volatile("tcgen05.alloc.cta_group::1.sync.aligned.shared::cta.b32 [%0], %1;" \
                 :: "r"((uint32_t)(smem_result_addr)), "r"((uint32_t)(nCols)) : "memory")
#define TCGEN05_DEALLOC(tmem_addr, nCols) \
    asm volatile("tcgen05.dealloc.cta_group::1.sync.aligned.b32 %0, %1;" :: "r"(tmem_addr), "r"((uint32_t)(nCols)))
#define TCGEN05_RELINQUISH() \
    asm volatile("tcgen05.relinquish_alloc_permit.cta_group::1.sync.aligned;")
#define TCGEN05_COMMIT(mbar_smem_addr) \
    asm volatile("tcgen05.commit.cta_group::1.mbarrier::arrive::one.shared::cluster.b64 [%0];" \
                 :: "r"((uint32_t)(mbar_smem_addr)) : "memory")
#define TCGEN05_WAIT_LD()      asm volatile("tcgen05.wait::ld.sync.aligned;" ::: "memory")
#define TCGEN05_FENCE_BEFORE() asm volatile("tcgen05.fence::before_thread_sync;" ::: "memory")
#define TCGEN05_FENCE_AFTER()  asm volatile("tcgen05.fence::after_thread_sync;" ::: "memory")

#define MMA_F16_SS(d_tmem, a_desc, b_desc, idesc, enable_d) do { \
    uint32_t _en = (enable_d); \
    asm volatile( \
        "{\n\t.reg .pred p;\n\t" \
        "setp.ne.u32 p, %4, 0;\n\t" \
        "tcgen05.mma.cta_group::1.kind::f16 [%0], %1, %2, %3, {%5, %5, %5, %5}, p;\n\t}" \
        :: "r"(d_tmem), "l"(a_desc), "l"(b_desc), "r"(idesc), "r"(_en), "r"(0u) : "memory"); \
} while (0)

#define TCGEN05_LD_32X32B_X32(r, tmem_addr) \
    asm volatile( \
        "tcgen05.ld.sync.aligned.32x32b.x32.b32 " \
        "{%0, %1, %2, %3, %4, %5, %6, %7, " \
        " %8, %9, %10, %11, %12, %13, %14, %15, " \
        " %16, %17, %18, %19, %20, %21, %22, %23, " \
        " %24, %25, %26, %27, %28, %29, %30, %31}, [%32];" \
        : "=r"((r)[0]),  "=r"((r)[1]),  "=r"((r)[2]),  "=r"((r)[3]), \
          "=r"((r)[4]),  "=r"((r)[5]),  "=r"((r)[6]),  "=r"((r)[7]), \
          "=r"((r)[8]),  "=r"((r)[9]),  "=r"((r)[10]), "=r"((r)[11]), \
          "=r"((r)[12]), "=r"((r)[13]), "=r"((r)[14]), "=r"((r)[15]), \
          "=r"((r)[16]), "=r"((r)[17]), "=r"((r)[18]), "=r"((r)[19]), \
          "=r"((r)[20]), "=r"((r)[21]), "=r"((r)[22]), "=r"((r)[23]), \
          "=r"((r)[24]), "=r"((r)[25]), "=r"((r)[26]), "=r"((r)[27]), \
          "=r"((r)[28]), "=r"((r)[29]), "=r"((r)[30]), "=r"((r)[31]) \
        : "r"(tmem_addr))

// ---------------- HMMA fallback helpers (sm_103 pass only; never selected) ----------
__device__ __forceinline__ void ldsm_x4(uint32_t addr, uint32_t& r0, uint32_t& r1,
                                        uint32_t& r2, uint32_t& r3) {
    asm volatile("ldmatrix.sync.aligned.m8n8.x4.shared.b16 {%0,%1,%2,%3}, [%4];"
                 : "=r"(r0), "=r"(r1), "=r"(r2), "=r"(r3) : "r"(addr));
}
__device__ __forceinline__ void mma16816(float* d, const uint32_t* a, const uint32_t* b) {
    asm volatile(
        "mma.sync.aligned.m16n8k16.row.col.f32.f16.f16.f32 "
        "{%0,%1,%2,%3},{%4,%5,%6,%7},{%8,%9},{%0,%1,%2,%3};"
        : "+f"(d[0]), "+f"(d[1]), "+f"(d[2]), "+f"(d[3])
        : "r"(a[0]), "r"(a[1]), "r"(a[2]), "r"(a[3]), "r"(b[0]), "r"(b[1]));
}
__device__ __forceinline__ void fill_fb(const __half* __restrict__ gA,
                                        const __half* __restrict__ gB,
                                        int k0, uint32_t aB) {
    const int tid = threadIdx.x;
    uint32_t bB = aB + 16384;
#pragma unroll
    for (int it = 0; it < 4; ++it) {
        int item = it * 256 + tid;
        int r = item >> 3, c = item & 7;
        CP_ASYNC16(aB + swz((uint32_t)(r * 128 + c * 16)), gA + (size_t)r * DIM + k0 + c * 8);
    }
#pragma unroll
    for (int it = 0; it < 4; ++it) {
        int item = it * 256 + tid;
        int r = item >> 3, c = item & 7;
        CP_ASYNC16(bB + swz((uint32_t)(r * 128 + c * 16)), gB + (size_t)r * DIM + k0 + c * 8);
    }
}
__device__ __forceinline__ void fb_consume(uint32_t aB, uint32_t bB, int w, int lane,
                                           float d[2][16][4]) {
    int g  = lane >> 3;
    int lr = lane & 7;
#pragma unroll
    for (int c = 0; c < 4; ++c) {
        uint32_t a[2][4];
#pragma unroll
        for (int t = 0; t < 2; ++t) {
            int row  = w * 32 + t * 16 + (g & 1) * 8 + lr;
            int unit = 2 * c + (g >> 1);
            ldsm_x4(aB + swz((uint32_t)(row * 128 + unit * 16)), a[t][0], a[t][1], a[t][2], a[t][3]);
        }
        uint32_t b[16][2];
#pragma unroll
        for (int j = 0; j < 8; ++j) {
            int row  = j * 16 + (g >> 1) * 8 + lr;
            int unit = 2 * c + (g & 1);
            ldsm_x4(bB + swz((uint32_t)(row * 128 + unit * 16)),
                    b[2 * j][0], b[2 * j][1], b[2 * j + 1][0], b[2 * j + 1][1]);
        }
#pragma unroll
        for (int t = 0; t < 2; ++t)
#pragma unroll
            for (int j = 0; j < 16; ++j) mma16816(d[t][j], a[t], b[j]);
    }
}
__device__ __forceinline__ void fb_gemm(const __half* gA, const __half* gB,
                                        uint32_t buf, int w, int lane, float d[2][16][4]) {
    fill_fb(gA, gB, 0, buf);
    asm volatile("cp.async.commit_group;" ::: "memory");
#pragma unroll 1
    for (int i = 0; i < NCHUNKS; ++i) {
        if (i < NCHUNKS - 1) {
            fill_fb(gA, gB, (i + 1) * KT, buf + (uint32_t)((i + 1) & 1) * 32768);
            asm volatile("cp.async.commit_group;" ::: "memory");
            asm volatile("cp.async.wait_group 1;" ::: "memory");
        } else {
            asm volatile("cp.async.wait_group 0;" ::: "memory");
        }
        __syncthreads();
        uint32_t aB = buf + (uint32_t)(i & 1) * 32768;
        if (w < 4) fb_consume(aB, aB + 16384, w, lane, d);
        __syncthreads();
    }
}

// convert one float4 of C into g_C16; gidx = global float4 index over 4 tensors
__device__ __forceinline__ void convert_c_item(size_t gidx,
                                               const float* __restrict__ C1,
                                               const float* __restrict__ C2,
                                               const float* __restrict__ C3,
                                               const float* __restrict__ C4) {
    int y = (int)(gidx >> 21);               // 2^21 float4 per tensor
    size_t rem = gidx & 2097151u;
    const float* src = (y == 0) ? C1 : (y == 1) ? C2 : (y == 2) ? C3 : C4;
    float4 v = reinterpret_cast<const float4*>(src)[rem];
    __half2 h0 = __floats2half2_rn(v.x, v.y);
    __half2 h1 = __floats2half2_rn(v.z, v.w);
    uint2 u;
    u.x = *reinterpret_cast<unsigned*>(&h0);
    u.y = *reinterpret_cast<unsigned*>(&h1);
    *reinterpret_cast<uint2*>(g_C16 + (size_t)y * CSTR + rem * 4) = u;
}

// ---------------- convert kernels ----------------
// P only (+ zero d_out). C1..C4 conversion is folded into gemm_a's idle warps.
__global__ void convert_p_kernel(const float* __restrict__ P, float* __restrict__ out) {
    size_t t = (size_t)blockIdx.x * 256 + threadIdx.x;
    size_t i = t * 4;
    float4 v = *(const float4*)(P + i);
    __half2 h0 = __floats2half2_rn(v.x, v.y);
    __half2 h1 = __floats2half2_rn(v.z, v.w);
    uint2 u;
    u.x = *reinterpret_cast<unsigned*>(&h0);
    u.y = *reinterpret_cast<unsigned*>(&h1);
    *reinterpret_cast<uint2*>(g_P16 + i) = u;
    if (t < (size_t)(B_ROWS * 4 / 4)) {
        reinterpret_cast<float4*>(out)[t] = make_float4(0.f, 0.f, 0.f, 0.f);
    }
}

__global__ void convert_w_kernel(const float* __restrict__ GWP,
                                 const float* __restrict__ GWC,
                                 const float* __restrict__ OW) {
    __shared__ float t[32][33];
    const float* src = (blockIdx.z == 0) ? GWP : (blockIdx.z == 1) ? GWC : OW;
    __half* dst = g_W16 + (size_t)blockIdx.z * DIM * DIM;
    int tx = threadIdx.x, ty = threadIdx.y;
#pragma unroll
    for (int j = 0; j < 4; j++) {
        int k = blockIdx.y * 32 + ty + j * 8;
        int n = blockIdx.x * 32 + tx;
        t[ty + j * 8][tx] = src[(size_t)k * DIM + n];
    }
    __syncthreads();
#pragma unroll
    for (int j = 0; j < 4; j++) {
        int n = blockIdx.x * 32 + ty + j * 8;
        int k = blockIdx.y * 32 + tx;
        dst[(size_t)n * DIM + k] = __float2half_rn(t[tx][ty + j * 8]);
    }
}

// ---------------- Stage A: WP = P@GWP + GateBias (fp16) ; WPO = P@OW + OutBias (fp32) -----
// grid (8 ny, 64 mb). N tile = 256, 4 TMA stages of 48 KB, 1 CTA/SM.
// Warp 0 thread 0 drives TMA+MMA; warps 1-7 convert this CTA's slice of C1..C4 meanwhile.
__global__ void __launch_bounds__(256, 1)
gemm_a_kernel(const float* __restrict__ GateBias, const float* __restrict__ OutBias,
              const float* __restrict__ C1, const float* __restrict__ C2,
              const float* __restrict__ C3, const float* __restrict__ C4,
              const __grid_constant__ CUtensorMap tmaP,
              const __grid_constant__ CUtensorMap tmaW) {
    extern __shared__ char smem_raw[];
    uint32_t sb = (smem_u32(smem_raw) + 1023u) & ~1023u;
    const uint32_t buf = sb + HDR_BYTES;
    const int ny = blockIdx.x;
    const int mb = blockIdx.y;
    const int n0 = (ny & 3) * 256;
    const bool isWP = (ny < 4);
    const float* bias = isWP ? GateBias : OutBias;
    const int tid = threadIdx.x;
    int wid = tid >> 5, lane = tid & 31;

#if USE_TC
    // barriers: full[0..3]@16..40, done[0..3]@48..72, fin@80
    if ((tid >> 5) == 0) { TCGEN05_ALLOC(sb, 256); TCGEN05_RELINQUISH(); }
    __syncthreads();
    uint32_t tmem;
    asm volatile("ld.shared.b32 %0, [%1];" : "=r"(tmem) : "r"(sb));
    if (tid == 0) {
#pragma unroll
        for (int p = 0; p < 4; ++p) { MBARRIER_INIT(sb + 16 + 8 * p, 1); MBARRIER_INIT(sb + 48 + 8 * p, 1); }
        MBARRIER_INIT(sb + 80, 1);
    }
    __syncthreads();

    if (tid == 0) {
        const int wrow = (isWP ? 0 : 2) * DIM + n0;
#pragma unroll
        for (int p = 0; p < 4; ++p) {
            uint32_t aB = buf + (uint32_t)p * STAGE_A;
            MBARRIER_EXPECT_TX(sb + 16 + 8 * p, 49152);
            TMA_LOAD_2D(aB,         &tmaP, p * KT, mb * TILE_M, sb + 16 + 8 * p);
            TMA_LOAD_2D(aB + 16384, &tmaW, p * KT, wrow,        sb + 16 + 8 * p);
        }
#pragma unroll 1
        for (int i = 0; i < NCHUNKS; ++i) {
            int b = i & 3;
            uint32_t aB = buf + (uint32_t)b * STAGE_A;
            MBARRIER_WAIT_PARITY(sb + 16 + 8 * b, (i >> 2) & 1);
            uint64_t ad = MAKE_SMEM_DESC(aB);
            uint64_t bd = MAKE_SMEM_DESC(aB + 16384);
#pragma unroll
            for (int ks = 0; ks < 4; ++ks) {
                uint32_t en = (i > 0 || ks > 0) ? 1u : 0u;
                MMA_F16_SS(tmem, ad + ks * 2, bd + ks * 2, IDESC256, en);
            }
            TCGEN05_COMMIT(sb + 48 + 8 * b);
            if (i + 4 < NCHUNKS) {
                MBARRIER_WAIT_PARITY(sb + 48 + 8 * b, (i >> 2) & 1);
                MBARRIER_EXPECT_TX(sb + 16 + 8 * b, 49152);
                TMA_LOAD_2D(aB,         &tmaP, (i + 4) * KT, mb * TILE_M, sb + 16 + 8 * b);
                TMA_LOAD_2D(aB + 16384, &tmaW, (i + 4) * KT, wrow,        sb + 16 + 8 * b);
            }
        }
        TCGEN05_COMMIT(sb + 80);
    } else if (tid >= 32) {
        // warps 1-7: convert this CTA's 16384-float4 slice of C1..C4 (overlaps mainloop)
        const size_t base = ((size_t)ny * 64 + mb) * 16384;
        for (int it = tid - 32; it < 16384; it += 224)
            convert_c_item(base + it, C1, C2, C3, C4);
    }
    MBARRIER_WAIT_PARITY(sb + 80, 0);
    TCGEN05_FENCE_AFTER();

    int sub = wid & 3, ch = wid >> 2;
    int row = mb * TILE_M + sub * 32 + lane;
#pragma unroll 1
    for (int c0 = 0; c0 < 128; c0 += 32) {
        uint32_t d[32];
        TCGEN05_LD_32X32B_X32(d, tmem + ch * 128 + c0);
        TCGEN05_WAIT_LD();
        int colg = n0 + ch * 128 + c0;
#pragma unroll
        for (int jj = 0; jj < 8; jj++) {
            float4 b = *(const float4*)(bias + colg + jj * 4);
            float4 o;
            o.x = __uint_as_float(d[jj * 4 + 0]) + b.x;
            o.y = __uint_as_float(d[jj * 4 + 1]) + b.y;
            o.z = __uint_as_float(d[jj * 4 + 2]) + b.z;
            o.w = __uint_as_float(d[jj * 4 + 3]) + b.w;
            if (isWP) {
                __half2 h0 = __floats2half2_rn(o.x, o.y);
                __half2 h1 = __floats2half2_rn(o.z, o.w);
                uint2 u;
                u.x = *reinterpret_cast<unsigned*>(&h0);
                u.y = *reinterpret_cast<unsigned*>(&h1);
                *reinterpret_cast<uint2*>(g_WPH + (size_t)row * DIM + colg + jj * 4) = u;
            } else {
                *(float4*)(g_WPO + (size_t)row * DIM + colg + jj * 4) = o;
            }
        }
    }
    TCGEN05_FENCE_BEFORE();
    __syncthreads();
    if ((threadIdx.x >> 5) == 0) TCGEN05_DEALLOC(tmem, 256);
#else
    {   // fallback: convert this CTA's C slice first (all 256 threads), then HMMA gemm
        const size_t base = ((size_t)ny * 64 + mb) * 16384;
        for (int it = tid; it < 16384; it += 256)
            convert_c_item(base + it, C1, C2, C3, C4);
        __syncthreads();
    }
    const __half* gA = g_P16 + (size_t)mb * TILE_M * DIM;
    const __half* gB = g_W16 + (size_t)(isWP ? 0 : 2) * DIM * DIM + (size_t)n0 * DIM;
#pragma unroll 1
    for (int ns = 0; ns < 2; ++ns) {
        const __half* gBs = gB + (size_t)ns * 128 * DIM;
        float d[2][16][4] = {};
        fb_gemm(gA, gBs, buf, wid, lane, d);
        if (wid < 4) {
            int colb = n0 + ns * 128;
#pragma unroll
            for (int t = 0; t < 2; ++t)
#pragma unroll
                for (int j = 0; j < 16; ++j) {
                    int row0 = mb * TILE_M + wid * 32 + t * 16 + (lane >> 2);
                    int col  = colb + j * 8 + (lane & 3) * 2;
                    float2 bb = *(const float2*)(bias + col);
                    float2 o0 = make_float2(d[t][j][0] + bb.x, d[t][j][1] + bb.y);
                    float2 o1 = make_float2(d[t][j][2] + bb.x, d[t][j][3] + bb.y);
                    if (isWP) {
                        *(__half2*)(g_WPH + (size_t)row0 * DIM + col)       = __floats2half2_rn(o0.x, o0.y);
                        *(__half2*)(g_WPH + (size_t)(row0 + 8) * DIM + col) = __floats2half2_rn(o1.x, o1.y);
                    } else {
                        *(float2*)(g_WPO + (size_t)row0 * DIM + col)       = o0;
                        *(float2*)(g_WPO + (size_t)(row0 + 8) * DIM + col) = o1;
                    }
                }
        }
    }
#endif
}

#if USE_TC
// prefetch the gemm_b epilogue working set into L2 (224 worker threads, 2560 lines).
__device__ __forceinline__ void prefetch_epi(int t, int mb, int nh, int kp) {
    for (int i = t; i < 2560; i += 224) {
        const void* p;
        if (i < 1024) {                 // wq: 128 rows x 8 lines (256 fp32)
            int r = i >> 3, l = i & 7;
            p = g_WPO + (size_t)(mb * TILE_M + r) * DIM + nh * 256 + l * 32;
        } else if (i < 1536) {          // wph: 128 rows x 4 lines (256 fp16)
            int j = i - 1024; int r = j >> 2, l = j & 3;
            p = g_WPH + (size_t)(mb * TILE_M + r) * DIM + nh * 256 + l * 64;
        } else {                        // c: 2 branches x 128 rows x 4 lines
            int j = i - 1536; int kk = j >> 9, rem = j & 511, r = rem >> 2, l = rem & 3;
            p = g_C16 + ((size_t)(kp * 2 + kk) * B_ROWS + mb * TILE_M + r) * DIM + nh * 256 + l * 64;
        }
        PREFETCH_L2(p);
    }
}
#endif

// ---------------- Stage B: 2 branches x 256 cols per CTA ----------------
// grid (4 nh, 64 mb, 2 kp), 256 threads, 1 CTA/SM. 3 TMA stages of 64 KB.
__global__ void __launch_bounds__(256, 1)
gemm_b_kernel(float* __restrict__ out,
              const __grid_constant__ CUtensorMap tmaC,
              const __grid_constant__ CUtensorMap tmaW) {
    extern __shared__ char smem_raw[];
    uint32_t sb = (smem_u32(smem_raw) + 1023u) & ~1023u;
    const uint32_t buf = sb + HDR_BYTES;
    const int nh = blockIdx.x;          // 0..3 (256-col slice)
    const int mb = blockIdx.y;
    const int kp = blockIdx.z;          // branch pair: k = kp*2 + {0,1}
    const int tid = threadIdx.x;
    int wid = tid >> 5, lane = tid & 31;

#if USE_TC
    // barriers: full[0..2]@16..32, done[0..2]@40..56, fin@64
    if ((tid >> 5) == 0) { TCGEN05_ALLOC(sb, 512); TCGEN05_RELINQUISH(); }
    __syncthreads();
    uint32_t tmem;
    asm volatile("ld.shared.b32 %0, [%1];" : "=r"(tmem) : "r"(sb));
    if (tid == 0) {
#pragma unroll
        for (int p = 0; p < 3; ++p) { MBARRIER_INIT(sb + 16 + 8 * p, 1); MBARRIER_INIT(sb + 40 + 8 * p, 1); }
        MBARRIER_INIT(sb + 64, 1);
    }
    __syncthreads();

    if (tid == 0) {
        const int arow0 = (kp * 2 + 0) * B_ROWS + mb * TILE_M;
        const int arow1 = (kp * 2 + 1) * B_ROWS + mb * TILE_M;
        const int brow  = DIM + nh * 256;
#pragma unroll
        for (int p = 0; p < 3; ++p) {
            uint32_t aB = buf + (uint32_t)p * STAGE_B;
            MBARRIER_EXPECT_TX(sb + 16 + 8 * p, 65536);
            TMA_LOAD_2D(aB,         &tmaC, p * KT, arow0, sb + 16 + 8 * p);
            TMA_LOAD_2D(aB + 16384, &tmaC, p * KT, arow1, sb + 16 + 8 * p);
            TMA_LOAD_2D(aB + 32768, &tmaW, p * KT, brow,  sb + 16 + 8 * p);
        }
#pragma unroll 1
        for (int i = 0; i < NCHUNKS; ++i) {
            int b = i % 3;
            int ph = (i / 3) & 1;
            uint32_t aB = buf + (uint32_t)b * STAGE_B;
            MBARRIER_WAIT_PARITY(sb + 16 + 8 * b, ph);
            uint64_t bd = MAKE_SMEM_DESC(aB + 32768);
#pragma unroll
            for (int kk = 0; kk < 2; ++kk) {
                uint64_t ad = MAKE_SMEM_DESC(aB + kk * 16384);
#pragma unroll
                for (int ks = 0; ks < 4; ++ks) {
                    uint32_t en = (i > 0 || ks > 0) ? 1u : 0u;
                    MMA_F16_SS(tmem + kk * 256, ad + ks * 2, bd + ks * 2, IDESC256, en);
                }
            }
            TCGEN05_COMMIT(sb + 40 + 8 * b);
            if (i + 3 < NCHUNKS) {
                MBARRIER_WAIT_PARITY(sb + 40 + 8 * b, ph);
                MBARRIER_EXPECT_TX(sb + 16 + 8 * b, 65536);
                TMA_LOAD_2D(aB,         &tmaC, (i + 3) * KT, arow0, sb + 16 + 8 * b);
                TMA_LOAD_2D(aB + 16384, &tmaC, (i + 3) * KT, arow1, sb + 16 + 8 * b);
                TMA_LOAD_2D(aB + 32768, &tmaW, (i + 3) * KT, brow,  sb + 16 + 8 * b);
            }
        }
        TCGEN05_COMMIT(sb + 64);
    } else if (tid >= 32) {
        prefetch_epi(tid - 32, mb, nh, kp);
    }
    MBARRIER_WAIT_PARITY(sb + 64, 0);
    TCGEN05_FENCE_AFTER();

    // 8-warp fused epilogue: sub = row group; chc = column half of the 256-col slice.
    int sub = wid & 3, chc = wid >> 2;
    int row = mb * TILE_M + sub * 32 + lane;
    const int coff = nh * 256 + chc * 128;
    const __half* wp_row = g_WPH + (size_t)row * DIM + coff;
    const float*  wq_row = g_WPO + (size_t)row * DIM + coff;
    float score[2] = {0.f, 0.f};
#pragma unroll 1
    for (int c0 = 0; c0 < 128; c0 += 32) {
        float wq[32];
        __half2 wph[16];
#pragma unroll
        for (int q = 0; q < 8; ++q) *(float4*)(wq + q * 4) = *(const float4*)(wq_row + c0 + q * 4);
#pragma unroll
        for (int q = 0; q < 4; ++q) *(uint4*)(wph + q * 4) = *(const uint4*)(wp_row + c0 + q * 8);
#pragma unroll
        for (int kk = 0; kk < 2; ++kk) {
            uint32_t d[32];
            TCGEN05_LD_32X32B_X32(d, tmem + kk * 256 + chc * 128 + c0);
            TCGEN05_WAIT_LD();
            const __half* c_row = g_C16 + ((size_t)(kp * 2 + kk) * B_ROWS + row) * DIM + coff;
            float sk = 0.f;
#pragma unroll
            for (int jj = 0; jj < 8; ++jj) {
                float2 wp01 = __half22float2(wph[jj * 2]);
                float2 wp23 = __half22float2(wph[jj * 2 + 1]);
                uint2 cu = *(const uint2*)(c_row + c0 + jj * 4);
                float2 cv01 = __half22float2(*reinterpret_cast<__half2*>(&cu.x));
                float2 cv23 = __half22float2(*reinterpret_cast<__half2*>(&cu.y));
                float z, g;
                z = __uint_as_float(d[jj * 4 + 0]) + wp01.x;
                g = __fdividef(1.f, 1.f + __expf(-z)); sk += cv01.x * g * wq[jj * 4 + 0];
                z = __uint_as_float(d[jj * 4 + 1]) + wp01.y;
                g = __fdividef(1.f, 1.f + __expf(-z)); sk += cv01.y * g * wq[jj * 4 + 1];
                z = __uint_as_float(d[jj * 4 + 2]) + wp23.x;
                g = __fdividef(1.f, 1.f + __expf(-z)); sk += cv23.x * g * wq[jj * 4 + 2];
                z = __uint_as_float(d[jj * 4 + 3]) + wp23.y;
                g = __fdividef(1.f, 1.f + __expf(-z)); sk += cv23.y * g * wq[jj * 4 + 3];
            }
            score[kk] += sk;
        }
    }
    atomicAdd(out + (size_t)row * 4 + kp * 2 + 0, score[0]);
    atomicAdd(out + (size_t)row * 4 + kp * 2 + 1, score[1]);

    TCGEN05_FENCE_BEFORE();
    __syncthreads();
    if ((threadIdx.x >> 5) == 0) TCGEN05_DEALLOC(tmem, 512);
#else
    const __half* gA = g_C16 + (size_t)kp * 2 * CSTR + (size_t)mb * TILE_M * DIM;
    const __half* gB = g_W16 + (size_t)1 * DIM * DIM + (size_t)nh * 256 * DIM;
#pragma unroll 1
    for (int kk = 0; kk < 2; ++kk) {
#pragma unroll 1
        for (int ns = 0; ns < 2; ++ns) {
            float d[2][16][4] = {};
            fb_gemm(gA + (size_t)kk * CSTR, gB + (size_t)ns * 128 * DIM, buf, wid, lane, d);
            if (wid < 4) {
                float s[4] = {0.f, 0.f, 0.f, 0.f};
#pragma unroll
                for (int t = 0; t < 2; ++t)
#pragma unroll
                    for (int j = 0; j < 16; ++j) {
                        int col = nh * 256 + ns * 128 + j * 8 + (lane & 3) * 2;
#pragma unroll
                        for (int h = 0; h < 2; ++h) {
                            int row = mb * TILE_M + wid * 32 + t * 16 + (lane >> 2) + h * 8;
                            float2 wp = __half22float2(*(const __half2*)(g_WPH + (size_t)row * DIM + col));
                            float2 cv = __half22float2(*(const __half2*)(g_C16 + ((size_t)(kp * 2 + kk) * B_ROWS + row) * DIM + col));
                            float2 wq = *(const float2*)(g_WPO + (size_t)row * DIM + col);
                            float z, g;
                            z = d[t][j][h * 2 + 0] + wp.x;
                            g = __fdividef(1.f, 1.f + __expf(-z)); s[t * 2 + h] += cv.x * g * wq.x;
                            z = d[t][j][h * 2 + 1] + wp.y;
                            g = __fdividef(1.f, 1.f + __expf(-z)); s[t * 2 + h] += cv.y * g * wq.y;
                        }
                    }
#pragma unroll
                for (int i = 0; i < 4; ++i) {
                    s[i] += __shfl_xor_sync(0xffffffff, s[i], 1);
                    s[i] += __shfl_xor_sync(0xffffffff, s[i], 2);
                }
                if ((lane & 3) == 0) {
#pragma unroll
                    for (int t = 0; t < 2; ++t)
#pragma unroll
                        for (int h = 0; h < 2; ++h) {
                            int row = mb * TILE_M + wid * 32 + t * 16 + (lane >> 2) + h * 8;
                            atomicAdd(out + (size_t)row * 4 + kp * 2 + kk, s[t * 2 + h]);
                        }
                }
            }
            __syncthreads();
        }
    }
#endif
}

// ---------------- host: tensormap construction ----------------
typedef CUresult (*PFN_encodeTiled)(
    CUtensorMap*, CUtensorMapDataType, cuuint32_t, void*,
    const cuuint64_t*, const cuuint64_t*, const cuuint32_t*, const cuuint32_t*,
    CUtensorMapInterleave, CUtensorMapSwizzle, CUtensorMapL2promotion, CUtensorMapFloatOOBfill);

static void make_map(PFN_encodeTiled enc, CUtensorMap* m, void* base,
                     unsigned long long rows, unsigned box_rows) {
    cuuint64_t dims[2]    = {(cuuint64_t)DIM, (cuuint64_t)rows};
    cuuint64_t strides[1] = {(cuuint64_t)DIM * 2};
    cuuint32_t box[2]     = {(cuuint32_t)KT, (cuuint32_t)box_rows};
    cuuint32_t es[2]      = {1, 1};
    enc(m, CU_TENSOR_MAP_DATA_TYPE_UINT16, 2, base, dims, strides, box, es,
        CU_TENSOR_MAP_INTERLEAVE_NONE, CU_TENSOR_MAP_SWIZZLE_128B,
        CU_TENSOR_MAP_L2_PROMOTION_L2_128B, CU_TENSOR_MAP_FLOAT_OOB_FILL_NONE);
}

extern "C" void kernel_launch(void* const* d_in, const int* in_sizes, int n_in,
                              void* d_out, int out_size) {
    const float* P   = (const float*)d_in[0];
    const float* C1  = (const float*)d_in[1];
    const float* C2  = (const float*)d_in[2];
    const float* C3  = (const float*)d_in[3];
    const float* C4  = (const float*)d_in[4];
    const float* GWP = (const float*)d_in[5];
    const float* GWC = (const float*)d_in[6];
    const float* GB  = (const float*)d_in[7];
    const float* OW  = (const float*)d_in[8];
    const float* OB  = (const float*)d_in[9];
    float* out = (float*)d_out;

    cudaFuncSetAttribute(gemm_a_kernel, cudaFuncAttributeMaxDynamicSharedMemorySize, SMEM_DYN);
    cudaFuncSetAttribute(gemm_b_kernel, cudaFuncAttributeMaxDynamicSharedMemorySize, SMEM_DYN);

    PFN_encodeTiled enc = nullptr;
    cudaDriverEntryPointQueryResult qres;
    cudaGetDriverEntryPoint("cuTensorMapEncodeTiled", (void**)&enc, cudaEnableDefault, &qres);
    void *pP = nullptr, *pC = nullptr, *pW = nullptr;
    cudaGetSymbolAddress(&pP, g_P16);
    cudaGetSymbolAddress(&pC, g_C16);
    cudaGetSymbolAddress(&pW, g_W16);
    CUtensorMap tmaP, tmaC, tmaW256;
    make_map(enc, &tmaP,    pP, (unsigned long long)B_ROWS,      128);
    make_map(enc, &tmaC,    pC, (unsigned long long)B_ROWS * 4,  128);
    make_map(enc, &tmaW256, pW, (unsigned long long)DIM * 3,     256);

    convert_p_kernel<<<B_ROWS * DIM / 4 / 256, 256>>>(P, out);
    convert_w_kernel<<<dim3(DIM / 32, DIM / 32, 3), dim3(32, 8)>>>(GWP, GWC, OW);
    gemm_a_kernel<<<dim3(8, B_ROWS / TILE_M), 256, SMEM_DYN>>>(GB, OB, C1, C2, C3, C4, tmaP, tmaW256);
    gemm_b_kernel<<<dim3(4, B_ROWS / TILE_M, 2), 256, SMEM_DYN>>>(out, tmaC, tmaW256);
}

// round 16
// speedup vs baseline: 1.2482x; 1.2482x over previous
#include <cuda_runtime.h>
#include <cuda.h>
#include <cuda_fp16.h>
#include <cstdint>

constexpr int B_ROWS = 8192;
constexpr int DIM    = 1024;
constexpr int TILE_M = 128;
constexpr int KT     = 64;
constexpr int NCHUNKS = DIM / KT;          // 16

constexpr uint32_t IDESC256 = (1u << 4) | ((256u / 8u) << 17) | ((128u / 16u) << 24);

constexpr uint32_t STAGE_A = 48 * 1024;    // gemm_a: A 16K + B(256 rows) 32K
constexpr uint32_t STAGE_B = 64 * 1024;    // gemm_b: A0 16K + A1 16K + B(256 rows) 32K
constexpr uint32_t HDR_BYTES = 1024;
constexpr uint32_t SMEM_DYN  = 1024 + HDR_BYTES + 192 * 1024;   // covers 4x48K and 3x64K

constexpr size_t CSTR = (size_t)B_ROWS * DIM;

__device__ __half g_P16[(size_t)B_ROWS * DIM];
__device__ __half g_C16[(size_t)4 * B_ROWS * DIM];
__device__ __half g_W16[(size_t)3 * DIM * DIM];
__device__ __half g_WPH[(size_t)B_ROWS * DIM];
__device__ float  g_WPO[(size_t)B_ROWS * DIM];

#if defined(__CUDA_ARCH__) && (defined(__CUDA_ARCH_FEAT_SM103_ALL) || defined(__CUDA_ARCH_FEAT_SM100_ALL) || defined(__CUDA_ARCH_FAMILY_SPECIFIC__))
#define USE_TC 1
#else
#define USE_TC 0
#endif

__device__ __forceinline__ uint32_t smem_u32(const void* p) {
    uint32_t a;
    asm("{ .reg .u64 t; cvta.to.shared.u64 t, %1; cvt.u32.u64 %0, t; }" : "=r"(a) : "l"(p));
    return a;
}
__device__ __forceinline__ uint32_t swz(uint32_t off) { return off ^ ((off >> 3) & 0x70); }

static constexpr uint64_t SMEM_DESC_BASE_SW128 =
    (uint64_t(2) << 61) | (uint64_t(1) << 46) | (uint64_t(64) << 32) | (uint64_t(1) << 16);
#define MAKE_SMEM_DESC(base_addr) \
    (SMEM_DESC_BASE_SW128 | ((uint64_t)((base_addr) >> 4) & 0x3FFF))

#define CP_ASYNC16(dst, src) \
    asm volatile("cp.async.cg.shared.global [%0], [%1], 16;" :: "r"(dst), "l"(src))

#define PREFETCH_L2(p) \
    asm volatile("prefetch.global.L2 [%0];" :: "l"(p))

#define MBARRIER_INIT(addr, count) \
    asm volatile("mbarrier.init.shared.b64 [%0], %1;" :: "r"((uint32_t)(addr)), "r"((uint32_t)(count)) : "memory")

#define MBARRIER_EXPECT_TX(addr, bytes) \
    asm volatile("mbarrier.arrive.expect_tx.shared.b64 _, [%0], %1;" \
                 :: "r"((uint32_t)(addr)), "r"((uint32_t)(bytes)) : "memory")

#define TMA_LOAD_2D(smem_addr, map_ptr, cx, cy, mbar) \
    asm volatile("cp.async.bulk.tensor.2d.shared::cta.global.tile.mbarrier::complete_tx::bytes " \
                 "[%0], [%1, {%2, %3}], [%4];" \
                 :: "r"((uint32_t)(smem_addr)), "l"(map_ptr), "r"((int)(cx)), "r"((int)(cy)), \
                    "r"((uint32_t)(mbar)) : "memory")

#define MBARRIER_WAIT_PARITY(mbar_smem_addr, phase_parity) do { \
    uint32_t _mbar = (uint32_t)(mbar_smem_addr); \
    uint32_t _parity = (uint32_t)(phase_parity); \
    uint32_t _done; \
    asm volatile( \
        "{\n\t.reg .pred p;\n\t" \
        "mbarrier.try_wait.parity.acquire.cta.shared::cta.b64 p, [%1], %2;\n\t" \
        "selp.b32 %0, 1, 0, p;\n\t}" \
        : "=r"(_done) : "r"(_mbar), "r"(_parity) : "memory"); \
    if (!_done) { \
        asm volatile( \
            "{\n\t.reg .pred P1;\n\t" \
            "WAIT_LOOP_%=:\n\t" \
            "mbarrier.try_wait.parity.acquire.cta.shared::cta.b64 P1, [%0], %1, 0x989680;\n\t" \
            "@P1 bra.uni WAIT_DONE_%=;\n\t" \
            "bra.uni WAIT_LOOP_%=;\n\t" \
            "WAIT_DONE_%=:\n\t}" \
            :: "r"(_mbar), "r"(_parity) : "memory"); \
    } \
} while (0)

#define TCGEN05_ALLOC(smem_result_addr, nCols) \
    asm volatile("tcgen05.alloc.cta_group::1.sync.aligned.shared::cta.b32 [%0], %1;" \
                 :: "r"((uint32_t)(smem_result_addr)), "r"((uint32_t)(nCols)) : "memory")
#define TCGEN05_DEALLOC(tmem_addr, nCols) \
    asm volatile("tcgen05.dealloc.cta_group::1.sync.aligned.b32 %0, %1;" :: "r"(tmem_addr), "r"((uint32_t)(nCols)))
#define TCGEN05_RELINQUISH() \
    asm volatile("tcgen05.relinquish_alloc_permit.cta_group::1.sync.aligned;")
#define TCGEN05_COMMIT(mbar_smem_addr) \
    asm volatile("tcgen05.commit.cta_group::1.mbarrier::arrive::one.shared::cluster.b64 [%0];" \
                 :: "r"((uint32_t)(mbar_smem_addr)) : "memory")
#define TCGEN05_WAIT_LD()      asm volatile("tcgen05.wait::ld.sync.aligned;" ::: "memory")
#define TCGEN05_FENCE_BEFORE() asm volatile("tcgen05.fence::before_thread_sync;" ::: "memory")
#define TCGEN05_FENCE_AFTER()  asm volatile("tcgen05.fence::after_thread_sync;" ::: "memory")

#define MMA_F16_SS(d_tmem, a_desc, b_desc, idesc, enable_d) do { \
    uint32_t _en = (enable_d); \
    asm volatile( \
        "{\n\t.reg .pred p;\n\t" \
        "setp.ne.u32 p, %4, 0;\n\t" \
        "tcgen05.mma.cta_group::1.kind::f16 [%0], %1, %2, %3, {%5, %5, %5, %5}, p;\n\t}" \
        :: "r"(d_tmem), "l"(a_desc), "l"(b_desc), "r"(idesc), "r"(_en), "r"(0u) : "memory"); \
} while (0)

#define TCGEN05_LD_32X32B_X32(r, tmem_addr) \
    asm volatile( \
        "tcgen05.ld.sync.aligned.32x32b.x32.b32 " \
        "{%0, %1, %2, %3, %4, %5, %6, %7, " \
        " %8, %9, %10, %11, %12, %13, %14, %15, " \
        " %16, %17, %18, %19, %20, %21, %22, %23, " \
        " %24, %25, %26, %27, %28, %29, %30, %31}, [%32];" \
        : "=r"((r)[0]),  "=r"((r)[1]),  "=r"((r)[2]),  "=r"((r)[3]), \
          "=r"((r)[4]),  "=r"((r)[5]),  "=r"((r)[6]),  "=r"((r)[7]), \
          "=r"((r)[8]),  "=r"((r)[9]),  "=r"((r)[10]), "=r"((r)[11]), \
          "=r"((r)[12]), "=r"((r)[13]), "=r"((r)[14]), "=r"((r)[15]), \
          "=r"((r)[16]), "=r"((r)[17]), "=r"((r)[18]), "=r"((r)[19]), \
          "=r"((r)[20]), "=r"((r)[21]), "=r"((r)[22]), "=r"((r)[23]), \
          "=r"((r)[24]), "=r"((r)[25]), "=r"((r)[26]), "=r"((r)[27]), \
          "=r"((r)[28]), "=r"((r)[29]), "=r"((r)[30]), "=r"((r)[31]) \
        : "r"(tmem_addr))

// ---------------- HMMA fallback helpers (sm_103 pass only; never selected) ----------
__device__ __forceinline__ void ldsm_x4(uint32_t addr, uint32_t& r0, uint32_t& r1,
                                        uint32_t& r2, uint32_t& r3) {
    asm volatile("ldmatrix.sync.aligned.m8n8.x4.shared.b16 {%0,%1,%2,%3}, [%4];"
                 : "=r"(r0), "=r"(r1), "=r"(r2), "=r"(r3) : "r"(addr));
}
__device__ __forceinline__ void mma16816(float* d, const uint32_t* a, const uint32_t* b) {
    asm volatile(
        "mma.sync.aligned.m16n8k16.row.col.f32.f16.f16.f32 "
        "{%0,%1,%2,%3},{%4,%5,%6,%7},{%8,%9},{%0,%1,%2,%3};"
        : "+f"(d[0]), "+f"(d[1]), "+f"(d[2]), "+f"(d[3])
        : "r"(a[0]), "r"(a[1]), "r"(a[2]), "r"(a[3]), "r"(b[0]), "r"(b[1]));
}
__device__ __forceinline__ void fill_fb(const __half* __restrict__ gA,
                                        const __half* __restrict__ gB,
                                        int k0, uint32_t aB) {
    const int tid = threadIdx.x;
    uint32_t bB = aB + 16384;
#pragma unroll
    for (int it = 0; it < 4; ++it) {
        int item = it * 256 + tid;
        int r = item >> 3, c = item & 7;
        CP_ASYNC16(aB + swz((uint32_t)(r * 128 + c * 16)), gA + (size_t)r * DIM + k0 + c * 8);
    }
#pragma unroll
    for (int it = 0; it < 4; ++it) {
        int item = it * 256 + tid;
        int r = item >> 3, c = item & 7;
        CP_ASYNC16(bB + swz((uint32_t)(r * 128 + c * 16)), gB + (size_t)r * DIM + k0 + c * 8);
    }
}
__device__ __forceinline__ void fb_consume(uint32_t aB, uint32_t bB, int w, int lane,
                                           float d[2][16][4]) {
    int g  = lane >> 3;
    int lr = lane & 7;
#pragma unroll
    for (int c = 0; c < 4; ++c) {
        uint32_t a[2][4];
#pragma unroll
        for (int t = 0; t < 2; ++t) {
            int row  = w * 32 + t * 16 + (g & 1) * 8 + lr;
            int unit = 2 * c + (g >> 1);
            ldsm_x4(aB + swz((uint32_t)(row * 128 + unit * 16)), a[t][0], a[t][1], a[t][2], a[t][3]);
        }
        uint32_t b[16][2];
#pragma unroll
        for (int j = 0; j < 8; ++j) {
            int row  = j * 16 + (g >> 1) * 8 + lr;
            int unit = 2 * c + (g & 1);
            ldsm_x4(bB + swz((uint32_t)(row * 128 + unit * 16)),
                    b[2 * j][0], b[2 * j][1], b[2 * j + 1][0], b[2 * j + 1][1]);
        }
#pragma unroll
        for (int t = 0; t < 2; ++t)
#pragma unroll
            for (int j = 0; j < 16; ++j) mma16816(d[t][j], a[t], b[j]);
    }
}
__device__ __forceinline__ void fb_gemm(const __half* gA, const __half* gB,
                                        uint32_t buf, int w, int lane, float d[2][16][4]) {
    fill_fb(gA, gB, 0, buf);
    asm volatile("cp.async.commit_group;" ::: "memory");
#pragma unroll 1
    for (int i = 0; i < NCHUNKS; ++i) {
        if (i < NCHUNKS - 1) {
            fill_fb(gA, gB, (i + 1) * KT, buf + (uint32_t)((i + 1) & 1) * 32768);
            asm volatile("cp.async.commit_group;" ::: "memory");
            asm volatile("cp.async.wait_group 1;" ::: "memory");
        } else {
            asm volatile("cp.async.wait_group 0;" ::: "memory");
        }
        __syncthreads();
        uint32_t aB = buf + (uint32_t)(i & 1) * 32768;
        if (w < 4) fb_consume(aB, aB + 16384, w, lane, d);
        __syncthreads();
    }
}

// ---- batched C conversion: CTA slice lies in ONE tensor; MLP-8 loads ----
// ci in [0,512): tensor = ci>>7, offset = (ci&127)*16384 float4s. nthreads strided.
__device__ __forceinline__ void convert_c_slice(int ci, int t, int nthreads,
                                                const float* __restrict__ C1,
                                                const float* __restrict__ C2,
                                                const float* __restrict__ C3,
                                                const float* __restrict__ C4) {
    const float* src = (ci < 128) ? C1 : (ci < 256) ? C2 : (ci < 384) ? C3 : C4;
    size_t off4 = (size_t)(ci & 127) * 16384;          // in float4 units
    const float4* s4 = reinterpret_cast<const float4*>(src) + off4;
    uint2* d2 = reinterpret_cast<uint2*>(g_C16 + (size_t)(ci >> 7) * CSTR + off4 * 4);
#pragma unroll 1
    for (int it0 = t; it0 < 16384; it0 += nthreads * 8) {
        float4 v[8];
#pragma unroll
        for (int q = 0; q < 8; ++q) {
            int it = it0 + q * nthreads;
            if (it < 16384) v[q] = s4[it];
        }
#pragma unroll
        for (int q = 0; q < 8; ++q) {
            int it = it0 + q * nthreads;
            if (it < 16384) {
                __half2 h0 = __floats2half2_rn(v[q].x, v[q].y);
                __half2 h1 = __floats2half2_rn(v[q].z, v[q].w);
                uint2 u;
                u.x = *reinterpret_cast<unsigned*>(&h0);
                u.y = *reinterpret_cast<unsigned*>(&h1);
                d2[it] = u;
            }
        }
    }
}

// ---------------- convert kernels ----------------
// P only (+ zero d_out). C1..C4 conversion is folded into gemm_a's idle warps.
__global__ void convert_p_kernel(const float* __restrict__ P, float* __restrict__ out) {
    size_t t = (size_t)blockIdx.x * 256 + threadIdx.x;
    size_t i = t * 4;
    float4 v = *(const float4*)(P + i);
    __half2 h0 = __floats2half2_rn(v.x, v.y);
    __half2 h1 = __floats2half2_rn(v.z, v.w);
    uint2 u;
    u.x = *reinterpret_cast<unsigned*>(&h0);
    u.y = *reinterpret_cast<unsigned*>(&h1);
    *reinterpret_cast<uint2*>(g_P16 + i) = u;
    if (t < (size_t)(B_ROWS * 4 / 4)) {
        reinterpret_cast<float4*>(out)[t] = make_float4(0.f, 0.f, 0.f, 0.f);
    }
}

__global__ void convert_w_kernel(const float* __restrict__ GWP,
                                 const float* __restrict__ GWC,
                                 const float* __restrict__ OW) {
    __shared__ float t[32][33];
    const float* src = (blockIdx.z == 0) ? GWP : (blockIdx.z == 1) ? GWC : OW;
    __half* dst = g_W16 + (size_t)blockIdx.z * DIM * DIM;
    int tx = threadIdx.x, ty = threadIdx.y;
#pragma unroll
    for (int j = 0; j < 4; j++) {
        int k = blockIdx.y * 32 + ty + j * 8;
        int n = blockIdx.x * 32 + tx;
        t[ty + j * 8][tx] = src[(size_t)k * DIM + n];
    }
    __syncthreads();
#pragma unroll
    for (int j = 0; j < 4; j++) {
        int n = blockIdx.x * 32 + ty + j * 8;
        int k = blockIdx.y * 32 + tx;
        dst[(size_t)n * DIM + k] = __float2half_rn(t[tx][ty + j * 8]);
    }
}

// ---------------- Stage A: WP = P@GWP + GateBias (fp16) ; WPO = P@OW + OutBias (fp32) -----
// grid (8 ny, 64 mb). N tile = 256, 4 TMA stages of 48 KB, 1 CTA/SM.
// Warp 0 thread 0 drives TMA+MMA; warps 1-7 convert this CTA's slice of C1..C4 meanwhile.
__global__ void __launch_bounds__(256, 1)
gemm_a_kernel(const float* __restrict__ GateBias, const float* __restrict__ OutBias,
              const float* __restrict__ C1, const float* __restrict__ C2,
              const float* __restrict__ C3, const float* __restrict__ C4,
              const __grid_constant__ CUtensorMap tmaP,
              const __grid_constant__ CUtensorMap tmaW) {
    extern __shared__ char smem_raw[];
    uint32_t sb = (smem_u32(smem_raw) + 1023u) & ~1023u;
    const uint32_t buf = sb + HDR_BYTES;
    const int ny = blockIdx.x;
    const int mb = blockIdx.y;
    const int n0 = (ny & 3) * 256;
    const bool isWP = (ny < 4);
    const float* bias = isWP ? GateBias : OutBias;
    const int tid = threadIdx.x;
    int wid = tid >> 5, lane = tid & 31;

#if USE_TC
    // barriers: full[0..3]@16..40, done[0..3]@48..72, fin@80
    if ((tid >> 5) == 0) { TCGEN05_ALLOC(sb, 256); TCGEN05_RELINQUISH(); }
    __syncthreads();
    uint32_t tmem;
    asm volatile("ld.shared.b32 %0, [%1];" : "=r"(tmem) : "r"(sb));
    if (tid == 0) {
#pragma unroll
        for (int p = 0; p < 4; ++p) { MBARRIER_INIT(sb + 16 + 8 * p, 1); MBARRIER_INIT(sb + 48 + 8 * p, 1); }
        MBARRIER_INIT(sb + 80, 1);
    }
    __syncthreads();

    if (tid == 0) {
        const int wrow = (isWP ? 0 : 2) * DIM + n0;
#pragma unroll
        for (int p = 0; p < 4; ++p) {
            uint32_t aB = buf + (uint32_t)p * STAGE_A;
            MBARRIER_EXPECT_TX(sb + 16 + 8 * p, 49152);
            TMA_LOAD_2D(aB,         &tmaP, p * KT, mb * TILE_M, sb + 16 + 8 * p);
            TMA_LOAD_2D(aB + 16384, &tmaW, p * KT, wrow,        sb + 16 + 8 * p);
        }
#pragma unroll 1
        for (int i = 0; i < NCHUNKS; ++i) {
            int b = i & 3;
            uint32_t aB = buf + (uint32_t)b * STAGE_A;
            MBARRIER_WAIT_PARITY(sb + 16 + 8 * b, (i >> 2) & 1);
            uint64_t ad = MAKE_SMEM_DESC(aB);
            uint64_t bd = MAKE_SMEM_DESC(aB + 16384);
#pragma unroll
            for (int ks = 0; ks < 4; ++ks) {
                uint32_t en = (i > 0 || ks > 0) ? 1u : 0u;
                MMA_F16_SS(tmem, ad + ks * 2, bd + ks * 2, IDESC256, en);
            }
            TCGEN05_COMMIT(sb + 48 + 8 * b);
            if (i + 4 < NCHUNKS) {
                MBARRIER_WAIT_PARITY(sb + 48 + 8 * b, (i >> 2) & 1);
                MBARRIER_EXPECT_TX(sb + 16 + 8 * b, 49152);
                TMA_LOAD_2D(aB,         &tmaP, (i + 4) * KT, mb * TILE_M, sb + 16 + 8 * b);
                TMA_LOAD_2D(aB + 16384, &tmaW, (i + 4) * KT, wrow,        sb + 16 + 8 * b);
            }
        }
        TCGEN05_COMMIT(sb + 80);
    } else if (tid >= 32) {
        // warps 1-7: convert this CTA's slice of C1..C4 with MLP-8 batching
        convert_c_slice(ny * 64 + mb, tid - 32, 224, C1, C2, C3, C4);
    }
    MBARRIER_WAIT_PARITY(sb + 80, 0);
    TCGEN05_FENCE_AFTER();

    int sub = wid & 3, ch = wid >> 2;
    int row = mb * TILE_M + sub * 32 + lane;
#pragma unroll 1
    for (int c0 = 0; c0 < 128; c0 += 32) {
        uint32_t d[32];
        TCGEN05_LD_32X32B_X32(d, tmem + ch * 128 + c0);
        TCGEN05_WAIT_LD();
        int colg = n0 + ch * 128 + c0;
#pragma unroll
        for (int jj = 0; jj < 8; jj++) {
            float4 b = *(const float4*)(bias + colg + jj * 4);
            float4 o;
            o.x = __uint_as_float(d[jj * 4 + 0]) + b.x;
            o.y = __uint_as_float(d[jj * 4 + 1]) + b.y;
            o.z = __uint_as_float(d[jj * 4 + 2]) + b.z;
            o.w = __uint_as_float(d[jj * 4 + 3]) + b.w;
            if (isWP) {
                __half2 h0 = __floats2half2_rn(o.x, o.y);
                __half2 h1 = __floats2half2_rn(o.z, o.w);
                uint2 u;
                u.x = *reinterpret_cast<unsigned*>(&h0);
                u.y = *reinterpret_cast<unsigned*>(&h1);
                *reinterpret_cast<uint2*>(g_WPH + (size_t)row * DIM + colg + jj * 4) = u;
            } else {
                *(float4*)(g_WPO + (size_t)row * DIM + colg + jj * 4) = o;
            }
        }
    }
    TCGEN05_FENCE_BEFORE();
    __syncthreads();
    if ((threadIdx.x >> 5) == 0) TCGEN05_DEALLOC(tmem, 256);
#else
    {   // fallback: convert this CTA's C slice first (all 256 threads), then HMMA gemm
        convert_c_slice(ny * 64 + mb, tid, 256, C1, C2, C3, C4);
        __syncthreads();
    }
    const __half* gA = g_P16 + (size_t)mb * TILE_M * DIM;
    const __half* gB = g_W16 + (size_t)(isWP ? 0 : 2) * DIM * DIM + (size_t)n0 * DIM;
#pragma unroll 1
    for (int ns = 0; ns < 2; ++ns) {
        const __half* gBs = gB + (size_t)ns * 128 * DIM;
        float d[2][16][4] = {};
        fb_gemm(gA, gBs, buf, wid, lane, d);
        if (wid < 4) {
            int colb = n0 + ns * 128;
#pragma unroll
            for (int t = 0; t < 2; ++t)
#pragma unroll
                for (int j = 0; j < 16; ++j) {
                    int row0 = mb * TILE_M + wid * 32 + t * 16 + (lane >> 2);
                    int col  = colb + j * 8 + (lane & 3) * 2;
                    float2 bb = *(const float2*)(bias + col);
                    float2 o0 = make_float2(d[t][j][0] + bb.x, d[t][j][1] + bb.y);
                    float2 o1 = make_float2(d[t][j][2] + bb.x, d[t][j][3] + bb.y);
                    if (isWP) {
                        *(__half2*)(g_WPH + (size_t)row0 * DIM + col)       = __floats2half2_rn(o0.x, o0.y);
                        *(__half2*)(g_WPH + (size_t)(row0 + 8) * DIM + col) = __floats2half2_rn(o1.x, o1.y);
                    } else {
                        *(float2*)(g_WPO + (size_t)row0 * DIM + col)       = o0;
                        *(float2*)(g_WPO + (size_t)(row0 + 8) * DIM + col) = o1;
                    }
                }
        }
    }
#endif
}

#if USE_TC
// prefetch the gemm_b epilogue working set into L2 (224 worker threads, 2560 lines).
__device__ __forceinline__ void prefetch_epi(int t, int mb, int nh, int kp) {
    for (int i = t; i < 2560; i += 224) {
        const void* p;
        if (i < 1024) {                 // wq: 128 rows x 8 lines (256 fp32)
            int r = i >> 3, l = i & 7;
            p = g_WPO + (size_t)(mb * TILE_M + r) * DIM + nh * 256 + l * 32;
        } else if (i < 1536) {          // wph: 128 rows x 4 lines (256 fp16)
            int j = i - 1024; int r = j >> 2, l = j & 3;
            p = g_WPH + (size_t)(mb * TILE_M + r) * DIM + nh * 256 + l * 64;
        } else {                        // c: 2 branches x 128 rows x 4 lines
            int j = i - 1536; int kk = j >> 9, rem = j & 511, r = rem >> 2, l = rem & 3;
            p = g_C16 + ((size_t)(kp * 2 + kk) * B_ROWS + mb * TILE_M + r) * DIM + nh * 256 + l * 64;
        }
        PREFETCH_L2(p);
    }
}
#endif

// ---------------- Stage B: 2 branches x 256 cols per CTA ----------------
// grid (4 nh, 64 mb, 2 kp), 256 threads, 1 CTA/SM. 3 TMA stages of 64 KB.
__global__ void __launch_bounds__(256, 1)
gemm_b_kernel(float* __restrict__ out,
              const __grid_constant__ CUtensorMap tmaC,
              const __grid_constant__ CUtensorMap tmaW) {
    extern __shared__ char smem_raw[];
    uint32_t sb = (smem_u32(smem_raw) + 1023u) & ~1023u;
    const uint32_t buf = sb + HDR_BYTES;
    const int nh = blockIdx.x;          // 0..3 (256-col slice)
    const int mb = blockIdx.y;
    const int kp = blockIdx.z;          // branch pair: k = kp*2 + {0,1}
    const int tid = threadIdx.x;
    int wid = tid >> 5, lane = tid & 31;

#if USE_TC
    // barriers: full[0..2]@16..32, done[0..2]@40..56, fin@64
    if ((tid >> 5) == 0) { TCGEN05_ALLOC(sb, 512); TCGEN05_RELINQUISH(); }
    __syncthreads();
    uint32_t tmem;
    asm volatile("ld.shared.b32 %0, [%1];" : "=r"(tmem) : "r"(sb));
    if (tid == 0) {
#pragma unroll
        for (int p = 0; p < 3; ++p) { MBARRIER_INIT(sb + 16 + 8 * p, 1); MBARRIER_INIT(sb + 40 + 8 * p, 1); }
        MBARRIER_INIT(sb + 64, 1);
    }
    __syncthreads();

    if (tid == 0) {
        const int arow0 = (kp * 2 + 0) * B_ROWS + mb * TILE_M;
        const int arow1 = (kp * 2 + 1) * B_ROWS + mb * TILE_M;
        const int brow  = DIM + nh * 256;
#pragma unroll
        for (int p = 0; p < 3; ++p) {
            uint32_t aB = buf + (uint32_t)p * STAGE_B;
            MBARRIER_EXPECT_TX(sb + 16 + 8 * p, 65536);
            TMA_LOAD_2D(aB,         &tmaC, p * KT, arow0, sb + 16 + 8 * p);
            TMA_LOAD_2D(aB + 16384, &tmaC, p * KT, arow1, sb + 16 + 8 * p);
            TMA_LOAD_2D(aB + 32768, &tmaW, p * KT, brow,  sb + 16 + 8 * p);
        }
#pragma unroll 1
        for (int i = 0; i < NCHUNKS; ++i) {
            int b = i % 3;
            int ph = (i / 3) & 1;
            uint32_t aB = buf + (uint32_t)b * STAGE_B;
            MBARRIER_WAIT_PARITY(sb + 16 + 8 * b, ph);
            uint64_t bd = MAKE_SMEM_DESC(aB + 32768);
#pragma unroll
            for (int kk = 0; kk < 2; ++kk) {
                uint64_t ad = MAKE_SMEM_DESC(aB + kk * 16384);
#pragma unroll
                for (int ks = 0; ks < 4; ++ks) {
                    uint32_t en = (i > 0 || ks > 0) ? 1u : 0u;
                    MMA_F16_SS(tmem + kk * 256, ad + ks * 2, bd + ks * 2, IDESC256, en);
                }
            }
            TCGEN05_COMMIT(sb + 40 + 8 * b);
            if (i + 3 < NCHUNKS) {
                MBARRIER_WAIT_PARITY(sb + 40 + 8 * b, ph);
                MBARRIER_EXPECT_TX(sb + 16 + 8 * b, 65536);
                TMA_LOAD_2D(aB,         &tmaC, (i + 3) * KT, arow0, sb + 16 + 8 * b);
                TMA_LOAD_2D(aB + 16384, &tmaC, (i + 3) * KT, arow1, sb + 16 + 8 * b);
                TMA_LOAD_2D(aB + 32768, &tmaW, (i + 3) * KT, brow,  sb + 16 + 8 * b);
            }
        }
        TCGEN05_COMMIT(sb + 64);
    } else if (tid >= 32) {
        prefetch_epi(tid - 32, mb, nh, kp);
    }
    MBARRIER_WAIT_PARITY(sb + 64, 0);
    TCGEN05_FENCE_AFTER();

    // 8-warp fused epilogue: sub = row group; chc = column half of the 256-col slice.
    int sub = wid & 3, chc = wid >> 2;
    int row = mb * TILE_M + sub * 32 + lane;
    const int coff = nh * 256 + chc * 128;
    const __half* wp_row = g_WPH + (size_t)row * DIM + coff;
    const float*  wq_row = g_WPO + (size_t)row * DIM + coff;
    float score[2] = {0.f, 0.f};
#pragma unroll 1
    for (int c0 = 0; c0 < 128; c0 += 32) {
        float wq[32];
        __half2 wph[16];
#pragma unroll
        for (int q = 0; q < 8; ++q) *(float4*)(wq + q * 4) = *(const float4*)(wq_row + c0 + q * 4);
#pragma unroll
        for (int q = 0; q < 4; ++q) *(uint4*)(wph + q * 4) = *(const uint4*)(wp_row + c0 + q * 8);
#pragma unroll
        for (int kk = 0; kk < 2; ++kk) {
            uint32_t d[32];
            TCGEN05_LD_32X32B_X32(d, tmem + kk * 256 + chc * 128 + c0);
            TCGEN05_WAIT_LD();
            const __half* c_row = g_C16 + ((size_t)(kp * 2 + kk) * B_ROWS + row) * DIM + coff;
            float sk = 0.f;
#pragma unroll
            for (int jj = 0; jj < 8; ++jj) {
                float2 wp01 = __half22float2(wph[jj * 2]);
                float2 wp23 = __half22float2(wph[jj * 2 + 1]);
                uint2 cu = *(const uint2*)(c_row + c0 + jj * 4);
                float2 cv01 = __half22float2(*reinterpret_cast<__half2*>(&cu.x));
                float2 cv23 = __half22float2(*reinterpret_cast<__half2*>(&cu.y));
                float z, g;
                z = __uint_as_float(d[jj * 4 + 0]) + wp01.x;
                g = __fdividef(1.f, 1.f + __expf(-z)); sk += cv01.x * g * wq[jj * 4 + 0];
                z = __uint_as_float(d[jj * 4 + 1]) + wp01.y;
                g = __fdividef(1.f, 1.f + __expf(-z)); sk += cv01.y * g * wq[jj * 4 + 1];
                z = __uint_as_float(d[jj * 4 + 2]) + wp23.x;
                g = __fdividef(1.f, 1.f + __expf(-z)); sk += cv23.x * g * wq[jj * 4 + 2];
                z = __uint_as_float(d[jj * 4 + 3]) + wp23.y;
                g = __fdividef(1.f, 1.f + __expf(-z)); sk += cv23.y * g * wq[jj * 4 + 3];
            }
            score[kk] += sk;
        }
    }
    atomicAdd(out + (size_t)row * 4 + kp * 2 + 0, score[0]);
    atomicAdd(out + (size_t)row * 4 + kp * 2 + 1, score[1]);

    TCGEN05_FENCE_BEFORE();
    __syncthreads();
    if ((threadIdx.x >> 5) == 0) TCGEN05_DEALLOC(tmem, 512);
#else
    const __half* gA = g_C16 + (size_t)kp * 2 * CSTR + (size_t)mb * TILE_M * DIM;
    const __half* gB = g_W16 + (size_t)1 * DIM * DIM + (size_t)nh * 256 * DIM;
#pragma unroll 1
    for (int kk = 0; kk < 2; ++kk) {
#pragma unroll 1
        for (int ns = 0; ns < 2; ++ns) {
            float d[2][16][4] = {};
            fb_gemm(gA + (size_t)kk * CSTR, gB + (size_t)ns * 128 * DIM, buf, wid, lane, d);
            if (wid < 4) {
                float s[4] = {0.f, 0.f, 0.f, 0.f};
#pragma unroll
                for (int t = 0; t < 2; ++t)
#pragma unroll
                    for (int j = 0; j < 16; ++j) {
                        int col = nh * 256 + ns * 128 + j * 8 + (lane & 3) * 2;
#pragma unroll
                        for (int h = 0; h < 2; ++h) {
                            int row = mb * TILE_M + wid * 32 + t * 16 + (lane >> 2) + h * 8;
                            float2 wp = __half22float2(*(const __half2*)(g_WPH + (size_t)row * DIM + col));
                            float2 cv = __half22float2(*(const __half2*)(g_C16 + ((size_t)(kp * 2 + kk) * B_ROWS + row) * DIM + col));
                            float2 wq = *(const float2*)(g_WPO + (size_t)row * DIM + col);
                            float z, g;
                            z = d[t][j][h * 2 + 0] + wp.x;
                            g = __fdividef(1.f, 1.f + __expf(-z)); s[t * 2 + h] += cv.x * g * wq.x;
                            z = d[t][j][h * 2 + 1] + wp.y;
                            g = __fdividef(1.f, 1.f + __expf(-z)); s[t * 2 + h] += cv.y * g * wq.y;
                        }
                    }
#pragma unroll
                for (int i = 0; i < 4; ++i) {
                    s[i] += __shfl_xor_sync(0xffffffff, s[i], 1);
                    s[i] += __shfl_xor_sync(0xffffffff, s[i], 2);
                }
                if ((lane & 3) == 0) {
#pragma unroll
                    for (int t = 0; t < 2; ++t)
#pragma unroll
                        for (int h = 0; h < 2; ++h) {
                            int row = mb * TILE_M + wid * 32 + t * 16 + (lane >> 2) + h * 8;
                            atomicAdd(out + (size_t)row * 4 + kp * 2 + kk, s[t * 2 + h]);
                        }
                }
            }
            __syncthreads();
        }
    }
#endif
}

// ---------------- host: tensormap construction ----------------
typedef CUresult (*PFN_encodeTiled)(
    CUtensorMap*, CUtensorMapDataType, cuuint32_t, void*,
    const cuuint64_t*, const cuuint64_t*, const cuuint32_t*, const cuuint32_t*,
    CUtensorMapInterleave, CUtensorMapSwizzle, CUtensorMapL2promotion, CUtensorMapFloatOOBfill);

static void make_map(PFN_encodeTiled enc, CUtensorMap* m, void* base,
                     unsigned long long rows, unsigned box_rows) {
    cuuint64_t dims[2]    = {(cuuint64_t)DIM, (cuuint64_t)rows};
    cuuint64_t strides[1] = {(cuuint64_t)DIM * 2};
    cuuint32_t box[2]     = {(cuuint32_t)KT, (cuuint32_t)box_rows};
    cuuint32_t es[2]      = {1, 1};
    enc(m, CU_TENSOR_MAP_DATA_TYPE_UINT16, 2, base, dims, strides, box, es,
        CU_TENSOR_MAP_INTERLEAVE_NONE, CU_TENSOR_MAP_SWIZZLE_128B,
        CU_TENSOR_MAP_L2_PROMOTION_L2_128B, CU_TENSOR_MAP_FLOAT_OOB_FILL_NONE);
}

extern "C" void kernel_launch(void* const* d_in, const int* in_sizes, int n_in,
                              void* d_out, int out_size) {
    const float* P   = (const float*)d_in[0];
    const float* C1  = (const float*)d_in[1];
    const float* C2  = (const float*)d_in[2];
    const float* C3  = (const float*)d_in[3];
    const float* C4  = (const float*)d_in[4];
    const float* GWP = (const float*)d_in[5];
    const float* GWC = (const float*)d_in[6];
    const float* GB  = (const float*)d_in[7];
    const float* OW  = (const float*)d_in[8];
    const float* OB  = (const float*)d_in[9];
    float* out = (float*)d_out;

    cudaFuncSetAttribute(gemm_a_kernel, cudaFuncAttributeMaxDynamicSharedMemorySize, SMEM_DYN);
    cudaFuncSetAttribute(gemm_b_kernel, cudaFuncAttributeMaxDynamicSharedMemorySize, SMEM_DYN);

    PFN_encodeTiled enc = nullptr;
    cudaDriverEntryPointQueryResult qres;
    cudaGetDriverEntryPoint("cuTensorMapEncodeTiled", (void**)&enc, cudaEnableDefault, &qres);
    void *pP = nullptr, *pC = nullptr, *pW = nullptr;
    cudaGetSymbolAddress(&pP, g_P16);
    cudaGetSymbolAddress(&pC, g_C16);
    cudaGetSymbolAddress(&pW, g_W16);
    CUtensorMap tmaP, tmaC, tmaW256;
    make_map(enc, &tmaP,    pP, (unsigned long long)B_ROWS,      128);
    make_map(enc, &tmaC,    pC, (unsigned long long)B_ROWS * 4,  128);
    make_map(enc, &tmaW256, pW, (unsigned long long)DIM * 3,     256);

    convert_p_kernel<<<B_ROWS * DIM / 4 / 256, 256>>>(P, out);
    convert_w_kernel<<<dim3(DIM / 32, DIM / 32, 3), dim3(32, 8)>>>(GWP, GWC, OW);
    gemm_a_kernel<<<dim3(8, B_ROWS / TILE_M), 256, SMEM_DYN>>>(GB, OB, C1, C2, C3, C4, tmaP, tmaW256);
    gemm_b_kernel<<<dim3(4, B_ROWS / TILE_M, 2), 256, SMEM_DYN>>>(out, tmaC, tmaW256);
}

// round 17
// speedup vs baseline: 1.2748x; 1.0213x over previous
#include <cuda_runtime.h>
#include <cuda.h>
#include <cuda_fp16.h>
#include <cstdint>

constexpr int B_ROWS = 8192;
constexpr int DIM    = 1024;
constexpr int TILE_M = 128;
constexpr int KT     = 64;
constexpr int NCHUNKS = DIM / KT;          // 16

constexpr uint32_t IDESC256 = (1u << 4) | ((256u / 8u) << 17) | ((128u / 16u) << 24);

constexpr uint32_t STAGE_A = 48 * 1024;    // gemm_a: A 16K + B(256 rows) 32K
constexpr uint32_t STAGE_B = 64 * 1024;    // gemm_b: A0 16K + A1 16K + B(256 rows) 32K
constexpr uint32_t HDR_BYTES = 1024;
constexpr uint32_t SMEM_DYN  = 1024 + HDR_BYTES + 192 * 1024;   // covers 4x48K and 3x64K

constexpr size_t CSTR = (size_t)B_ROWS * DIM;

__device__ __half g_P16[(size_t)B_ROWS * DIM];
__device__ __half g_C16[(size_t)4 * B_ROWS * DIM];
__device__ __half g_W16[(size_t)3 * DIM * DIM];
__device__ __half g_WPH[(size_t)B_ROWS * DIM];
__device__ float  g_WPO[(size_t)B_ROWS * DIM];

#if defined(__CUDA_ARCH__) && (defined(__CUDA_ARCH_FEAT_SM103_ALL) || defined(__CUDA_ARCH_FEAT_SM100_ALL) || defined(__CUDA_ARCH_FAMILY_SPECIFIC__))
#define USE_TC 1
#else
#define USE_TC 0
#endif

__device__ __forceinline__ uint32_t smem_u32(const void* p) {
    uint32_t a;
    asm("{ .reg .u64 t; cvta.to.shared.u64 t, %1; cvt.u32.u64 %0, t; }" : "=r"(a) : "l"(p));
    return a;
}
__device__ __forceinline__ uint32_t swz(uint32_t off) { return off ^ ((off >> 3) & 0x70); }

static constexpr uint64_t SMEM_DESC_BASE_SW128 =
    (uint64_t(2) << 61) | (uint64_t(1) << 46) | (uint64_t(64) << 32) | (uint64_t(1) << 16);
#define MAKE_SMEM_DESC(base_addr) \
    (SMEM_DESC_BASE_SW128 | ((uint64_t)((base_addr) >> 4) & 0x3FFF))

#define CP_ASYNC16(dst, src) \
    asm volatile("cp.async.cg.shared.global [%0], [%1], 16;" :: "r"(dst), "l"(src))

#define PREFETCH_L2(p) \
    asm volatile("prefetch.global.L2 [%0];" :: "l"(p))

#define MBARRIER_INIT(addr, count) \
    asm volatile("mbarrier.init.shared.b64 [%0], %1;" :: "r"((uint32_t)(addr)), "r"((uint32_t)(count)) : "memory")

#define MBARRIER_EXPECT_TX(addr, bytes) \
    asm volatile("mbarrier.arrive.expect_tx.shared.b64 _, [%0], %1;" \
                 :: "r"((uint32_t)(addr)), "r"((uint32_t)(bytes)) : "memory")

#define TMA_LOAD_2D(smem_addr, map_ptr, cx, cy, mbar) \
    asm volatile("cp.async.bulk.tensor.2d.shared::cta.global.tile.mbarrier::complete_tx::bytes " \
                 "[%0], [%1, {%2, %3}], [%4];" \
                 :: "r"((uint32_t)(smem_addr)), "l"(map_ptr), "r"((int)(cx)), "r"((int)(cy)), \
                    "r"((uint32_t)(mbar)) : "memory")

#define MBARRIER_WAIT_PARITY(mbar_smem_addr, phase_parity) do { \
    uint32_t _mbar = (uint32_t)(mbar_smem_addr); \
    uint32_t _parity = (uint32_t)(phase_parity); \
    uint32_t _done; \
    asm volatile( \
        "{\n\t.reg .pred p;\n\t" \
        "mbarrier.try_wait.parity.acquire.cta.shared::cta.b64 p, [%1], %2;\n\t" \
        "selp.b32 %0, 1, 0, p;\n\t}" \
        : "=r"(_done) : "r"(_mbar), "r"(_parity) : "memory"); \
    if (!_done) { \
        asm volatile( \
            "{\n\t.reg .pred P1;\n\t" \
            "WAIT_LOOP_%=:\n\t" \
            "mbarrier.try_wait.parity.acquire.cta.shared::cta.b64 P1, [%0], %1, 0x989680;\n\t" \
            "@P1 bra.uni WAIT_DONE_%=;\n\t" \
            "bra.uni WAIT_LOOP_%=;\n\t" \
            "WAIT_DONE_%=:\n\t}" \
            :: "r"(_mbar), "r"(_parity) : "memory"); \
    } \
} while (0)

#define TCGEN05_ALLOC(smem_result_addr, nCols) \
    asm volatile("tcgen05.alloc.cta_group::1.sync.aligned.shared::cta.b32 [%0], %1;" \
                 :: "r"((uint32_t)(smem_result_addr)), "r"((uint32_t)(nCols)) : "memory")
#define TCGEN05_DEALLOC(tmem_addr, nCols) \
    asm volatile("tcgen05.dealloc.cta_group::1.sync.aligned.b32 %0, %1;" :: "r"(tmem_addr), "r"((uint32_t)(nCols)))
#define TCGEN05_RELINQUISH() \
    asm volatile("tcgen05.relinquish_alloc_permit.cta_group::1.sync.aligned;")
#define TCGEN05_COMMIT(mbar_smem_addr) \
    asm volatile("tcgen05.commit.cta_group::1.mbarrier::arrive::one.shared::cluster.b64 [%0];" \
                 :: "r"((uint32_t)(mbar_smem_addr)) : "memory")
#define TCGEN05_WAIT_LD()      asm volatile("tcgen05.wait::ld.sync.aligned;" ::: "memory")
#define TCGEN05_FENCE_BEFORE() asm volatile("tcgen05.fence::before_thread_sync;" ::: "memory")
#define TCGEN05_FENCE_AFTER()  asm volatile("tcgen05.fence::after_thread_sync;" ::: "memory")

#define MMA_F16_SS(d_tmem, a_desc, b_desc, idesc, enable_d) do { \
    uint32_t _en = (enable_d); \
    asm volatile( \
        "{\n\t.reg .pred p;\n\t" \
        "setp.ne.u32 p, %4, 0;\n\t" \
        "tcgen05.mma.cta_group::1.kind::f16 [%0], %1, %2, %3, {%5, %5, %5, %5}, p;\n\t}" \
        :: "r"(d_tmem), "l"(a_desc), "l"(b_desc), "r"(idesc), "r"(_en), "r"(0u) : "memory"); \
} while (0)

#define TCGEN05_LD_32X32B_X32(r, tmem_addr) \
    asm volatile( \
        "tcgen05.ld.sync.aligned.32x32b.x32.b32 " \
        "{%0, %1, %2, %3, %4, %5, %6, %7, " \
        " %8, %9, %10, %11, %12, %13, %14, %15, " \
        " %16, %17, %18, %19, %20, %21, %22, %23, " \
        " %24, %25, %26, %27, %28, %29, %30, %31}, [%32];" \
        : "=r"((r)[0]),  "=r"((r)[1]),  "=r"((r)[2]),  "=r"((r)[3]), \
          "=r"((r)[4]),  "=r"((r)[5]),  "=r"((r)[6]),  "=r"((r)[7]), \
          "=r"((r)[8]),  "=r"((r)[9]),  "=r"((r)[10]), "=r"((r)[11]), \
          "=r"((r)[12]), "=r"((r)[13]), "=r"((r)[14]), "=r"((r)[15]), \
          "=r"((r)[16]), "=r"((r)[17]), "=r"((r)[18]), "=r"((r)[19]), \
          "=r"((r)[20]), "=r"((r)[21]), "=r"((r)[22]), "=r"((r)[23]), \
          "=r"((r)[24]), "=r"((r)[25]), "=r"((r)[26]), "=r"((r)[27]), \
          "=r"((r)[28]), "=r"((r)[29]), "=r"((r)[30]), "=r"((r)[31]) \
        : "r"(tmem_addr))

// ---------------- HMMA fallback helpers (sm_103 pass only; never selected) ----------
__device__ __forceinline__ void ldsm_x4(uint32_t addr, uint32_t& r0, uint32_t& r1,
                                        uint32_t& r2, uint32_t& r3) {
    asm volatile("ldmatrix.sync.aligned.m8n8.x4.shared.b16 {%0,%1,%2,%3}, [%4];"
                 : "=r"(r0), "=r"(r1), "=r"(r2), "=r"(r3) : "r"(addr));
}
__device__ __forceinline__ void mma16816(float* d, const uint32_t* a, const uint32_t* b) {
    asm volatile(
        "mma.sync.aligned.m16n8k16.row.col.f32.f16.f16.f32 "
        "{%0,%1,%2,%3},{%4,%5,%6,%7},{%8,%9},{%0,%1,%2,%3};"
        : "+f"(d[0]), "+f"(d[1]), "+f"(d[2]), "+f"(d[3])
        : "r"(a[0]), "r"(a[1]), "r"(a[2]), "r"(a[3]), "r"(b[0]), "r"(b[1]));
}
__device__ __forceinline__ void fill_fb(const __half* __restrict__ gA,
                                        const __half* __restrict__ gB,
                                        int k0, uint32_t aB) {
    const int tid = threadIdx.x;
    uint32_t bB = aB + 16384;
#pragma unroll
    for (int it = 0; it < 4; ++it) {
        int item = it * 256 + tid;
        int r = item >> 3, c = item & 7;
        CP_ASYNC16(aB + swz((uint32_t)(r * 128 + c * 16)), gA + (size_t)r * DIM + k0 + c * 8);
    }
#pragma unroll
    for (int it = 0; it < 4; ++it) {
        int item = it * 256 + tid;
        int r = item >> 3, c = item & 7;
        CP_ASYNC16(bB + swz((uint32_t)(r * 128 + c * 16)), gB + (size_t)r * DIM + k0 + c * 8);
    }
}
__device__ __forceinline__ void fb_consume(uint32_t aB, uint32_t bB, int w, int lane,
                                           float d[2][16][4]) {
    int g  = lane >> 3;
    int lr = lane & 7;
#pragma unroll
    for (int c = 0; c < 4; ++c) {
        uint32_t a[2][4];
#pragma unroll
        for (int t = 0; t < 2; ++t) {
            int row  = w * 32 + t * 16 + (g & 1) * 8 + lr;
            int unit = 2 * c + (g >> 1);
            ldsm_x4(aB + swz((uint32_t)(row * 128 + unit * 16)), a[t][0], a[t][1], a[t][2], a[t][3]);
        }
        uint32_t b[16][2];
#pragma unroll
        for (int j = 0; j < 8; ++j) {
            int row  = j * 16 + (g >> 1) * 8 + lr;
            int unit = 2 * c + (g & 1);
            ldsm_x4(bB + swz((uint32_t)(row * 128 + unit * 16)),
                    b[2 * j][0], b[2 * j][1], b[2 * j + 1][0], b[2 * j + 1][1]);
        }
#pragma unroll
        for (int t = 0; t < 2; ++t)
#pragma unroll
            for (int j = 0; j < 16; ++j) mma16816(d[t][j], a[t], b[j]);
    }
}
__device__ __forceinline__ void fb_gemm(const __half* gA, const __half* gB,
                                        uint32_t buf, int w, int lane, float d[2][16][4]) {
    fill_fb(gA, gB, 0, buf);
    asm volatile("cp.async.commit_group;" ::: "memory");
#pragma unroll 1
    for (int i = 0; i < NCHUNKS; ++i) {
        if (i < NCHUNKS - 1) {
            fill_fb(gA, gB, (i + 1) * KT, buf + (uint32_t)((i + 1) & 1) * 32768);
            asm volatile("cp.async.commit_group;" ::: "memory");
            asm volatile("cp.async.wait_group 1;" ::: "memory");
        } else {
            asm volatile("cp.async.wait_group 0;" ::: "memory");
        }
        __syncthreads();
        uint32_t aB = buf + (uint32_t)(i & 1) * 32768;
        if (w < 4) fb_consume(aB, aB + 16384, w, lane, d);
        __syncthreads();
    }
}

// ---- batched C conversion: CTA slice lies in ONE tensor; MLP-8 loads ----
__device__ __forceinline__ void convert_c_slice(int ci, int t, int nthreads,
                                                const float* __restrict__ C1,
                                                const float* __restrict__ C2,
                                                const float* __restrict__ C3,
                                                const float* __restrict__ C4) {
    const float* src = (ci < 128) ? C1 : (ci < 256) ? C2 : (ci < 384) ? C3 : C4;
    size_t off4 = (size_t)(ci & 127) * 16384;          // in float4 units
    const float4* s4 = reinterpret_cast<const float4*>(src) + off4;
    uint2* d2 = reinterpret_cast<uint2*>(g_C16 + (size_t)(ci >> 7) * CSTR + off4 * 4);
#pragma unroll 1
    for (int it0 = t; it0 < 16384; it0 += nthreads * 8) {
        float4 v[8];
#pragma unroll
        for (int q = 0; q < 8; ++q) {
            int it = it0 + q * nthreads;
            if (it < 16384) v[q] = s4[it];
        }
#pragma unroll
        for (int q = 0; q < 8; ++q) {
            int it = it0 + q * nthreads;
            if (it < 16384) {
                __half2 h0 = __floats2half2_rn(v[q].x, v[q].y);
                __half2 h1 = __floats2half2_rn(v[q].z, v[q].w);
                uint2 u;
                u.x = *reinterpret_cast<unsigned*>(&h0);
                u.y = *reinterpret_cast<unsigned*>(&h1);
                d2[it] = u;
            }
        }
    }
}

// ---------------- convert kernels ----------------
__global__ void convert_p_kernel(const float* __restrict__ P, float* __restrict__ out) {
    size_t t = (size_t)blockIdx.x * 256 + threadIdx.x;
    size_t i = t * 4;
    float4 v = *(const float4*)(P + i);
    __half2 h0 = __floats2half2_rn(v.x, v.y);
    __half2 h1 = __floats2half2_rn(v.z, v.w);
    uint2 u;
    u.x = *reinterpret_cast<unsigned*>(&h0);
    u.y = *reinterpret_cast<unsigned*>(&h1);
    *reinterpret_cast<uint2*>(g_P16 + i) = u;
    if (t < (size_t)(B_ROWS * 4 / 4)) {
        reinterpret_cast<float4*>(out)[t] = make_float4(0.f, 0.f, 0.f, 0.f);
    }
}

__global__ void convert_w_kernel(const float* __restrict__ GWP,
                                 const float* __restrict__ GWC,
                                 const float* __restrict__ OW) {
    __shared__ float t[32][33];
    const float* src = (blockIdx.z == 0) ? GWP : (blockIdx.z == 1) ? GWC : OW;
    __half* dst = g_W16 + (size_t)blockIdx.z * DIM * DIM;
    int tx = threadIdx.x, ty = threadIdx.y;
#pragma unroll
    for (int j = 0; j < 4; j++) {
        int k = blockIdx.y * 32 + ty + j * 8;
        int n = blockIdx.x * 32 + tx;
        t[ty + j * 8][tx] = src[(size_t)k * DIM + n];
    }
    __syncthreads();
#pragma unroll
    for (int j = 0; j < 4; j++) {
        int n = blockIdx.x * 32 + ty + j * 8;
        int k = blockIdx.y * 32 + tx;
        dst[(size_t)n * DIM + k] = __float2half_rn(t[tx][ty + j * 8]);
    }
}

// ---------------- Stage A: WP = P@GWP + GateBias (fp16) ; WPO = P@OW + OutBias (fp32) -----
// grid (8 ny, 64 mb). N tile = 256, 4 TMA stages of 48 KB, 1 CTA/SM.
// Warp 0 thread 0 drives TMA+MMA; warps 1-7 convert this CTA's slice of C1..C4 meanwhile.
__global__ void __launch_bounds__(256, 1)
gemm_a_kernel(const float* __restrict__ GateBias, const float* __restrict__ OutBias,
              const float* __restrict__ C1, const float* __restrict__ C2,
              const float* __restrict__ C3, const float* __restrict__ C4,
              const __grid_constant__ CUtensorMap tmaP,
              const __grid_constant__ CUtensorMap tmaW) {
    extern __shared__ char smem_raw[];
    uint32_t sb = (smem_u32(smem_raw) + 1023u) & ~1023u;
    const uint32_t buf = sb + HDR_BYTES;
    const int ny = blockIdx.x;
    const int mb = blockIdx.y;
    const int n0 = (ny & 3) * 256;
    const bool isWP = (ny < 4);
    const float* bias = isWP ? GateBias : OutBias;
    const int tid = threadIdx.x;
    int wid = tid >> 5, lane = tid & 31;

#if USE_TC
    // barriers: full[0..3]@16..40, done[0..3]@48..72, fin@80
    if ((tid >> 5) == 0) { TCGEN05_ALLOC(sb, 256); TCGEN05_RELINQUISH(); }
    __syncthreads();
    uint32_t tmem;
    asm volatile("ld.shared.b32 %0, [%1];" : "=r"(tmem) : "r"(sb));
    if (tid == 0) {
#pragma unroll
        for (int p = 0; p < 4; ++p) { MBARRIER_INIT(sb + 16 + 8 * p, 1); MBARRIER_INIT(sb + 48 + 8 * p, 1); }
        MBARRIER_INIT(sb + 80, 1);
    }
    __syncthreads();

    if (tid == 0) {
        const int wrow = (isWP ? 0 : 2) * DIM + n0;
        // prologue: 3 buffers in flight (4th filled at iter 0 without waiting)
#pragma unroll
        for (int p = 0; p < 3; ++p) {
            uint32_t aB = buf + (uint32_t)p * STAGE_A;
            MBARRIER_EXPECT_TX(sb + 16 + 8 * p, 49152);
            TMA_LOAD_2D(aB,         &tmaP, p * KT, mb * TILE_M, sb + 16 + 8 * p);
            TMA_LOAD_2D(aB + 16384, &tmaW, p * KT, wrow,        sb + 16 + 8 * p);
        }
#pragma unroll 1
        for (int i = 0; i < NCHUNKS; ++i) {
            int b = i & 3;
            uint32_t aB = buf + (uint32_t)b * STAGE_A;
            MBARRIER_WAIT_PARITY(sb + 16 + 8 * b, (i >> 2) & 1);
            uint64_t ad = MAKE_SMEM_DESC(aB);
            uint64_t bd = MAKE_SMEM_DESC(aB + 16384);
#pragma unroll
            for (int ks = 0; ks < 4; ++ks) {
                uint32_t en = (i > 0 || ks > 0) ? 1u : 0u;
                MMA_F16_SS(tmem, ad + ks * 2, bd + ks * 2, IDESC256, en);
            }
            TCGEN05_COMMIT(sb + 48 + 8 * b);
            // refill chunk i+3 into buffer (i+3)&3 == (i-1)&3: gated on done(i-1), ~free
            if (i + 3 < NCHUNKS) {
                int j = i + 3, bb = j & 3;
                uint32_t jB = buf + (uint32_t)bb * STAGE_A;
                if (i >= 1) MBARRIER_WAIT_PARITY(sb + 48 + 8 * bb, ((i - 1) >> 2) & 1);
                MBARRIER_EXPECT_TX(sb + 16 + 8 * bb, 49152);
                TMA_LOAD_2D(jB,         &tmaP, j * KT, mb * TILE_M, sb + 16 + 8 * bb);
                TMA_LOAD_2D(jB + 16384, &tmaW, j * KT, wrow,        sb + 16 + 8 * bb);
            }
        }
        TCGEN05_COMMIT(sb + 80);
    } else if (tid >= 32) {
        // warps 1-7: convert this CTA's slice of C1..C4 with MLP-8 batching
        convert_c_slice(ny * 64 + mb, tid - 32, 224, C1, C2, C3, C4);
    }
    MBARRIER_WAIT_PARITY(sb + 80, 0);
    TCGEN05_FENCE_AFTER();

    int sub = wid & 3, ch = wid >> 2;
    int row = mb * TILE_M + sub * 32 + lane;
#pragma unroll 1
    for (int c0 = 0; c0 < 128; c0 += 32) {
        uint32_t d[32];
        TCGEN05_LD_32X32B_X32(d, tmem + ch * 128 + c0);
        TCGEN05_WAIT_LD();
        int colg = n0 + ch * 128 + c0;
#pragma unroll
        for (int jj = 0; jj < 8; jj++) {
            float4 b = *(const float4*)(bias + colg + jj * 4);
            float4 o;
            o.x = __uint_as_float(d[jj * 4 + 0]) + b.x;
            o.y = __uint_as_float(d[jj * 4 + 1]) + b.y;
            o.z = __uint_as_float(d[jj * 4 + 2]) + b.z;
            o.w = __uint_as_float(d[jj * 4 + 3]) + b.w;
            if (isWP) {
                __half2 h0 = __floats2half2_rn(o.x, o.y);
                __half2 h1 = __floats2half2_rn(o.z, o.w);
                uint2 u;
                u.x = *reinterpret_cast<unsigned*>(&h0);
                u.y = *reinterpret_cast<unsigned*>(&h1);
                *reinterpret_cast<uint2*>(g_WPH + (size_t)row * DIM + colg + jj * 4) = u;
            } else {
                *(float4*)(g_WPO + (size_t)row * DIM + colg + jj * 4) = o;
            }
        }
    }
    TCGEN05_FENCE_BEFORE();
    __syncthreads();
    if ((threadIdx.x >> 5) == 0) TCGEN05_DEALLOC(tmem, 256);
#else
    {   // fallback: convert this CTA's C slice first (all 256 threads), then HMMA gemm
        convert_c_slice(ny * 64 + mb, tid, 256, C1, C2, C3, C4);
        __syncthreads();
    }
    const __half* gA = g_P16 + (size_t)mb * TILE_M * DIM;
    const __half* gB = g_W16 + (size_t)(isWP ? 0 : 2) * DIM * DIM + (size_t)n0 * DIM;
#pragma unroll 1
    for (int ns = 0; ns < 2; ++ns) {
        const __half* gBs = gB + (size_t)ns * 128 * DIM;
        float d[2][16][4] = {};
        fb_gemm(gA, gBs, buf, wid, lane, d);
        if (wid < 4) {
            int colb = n0 + ns * 128;
#pragma unroll
            for (int t = 0; t < 2; ++t)
#pragma unroll
                for (int j = 0; j < 16; ++j) {
                    int row0 = mb * TILE_M + wid * 32 + t * 16 + (lane >> 2);
                    int col  = colb + j * 8 + (lane & 3) * 2;
                    float2 bb = *(const float2*)(bias + col);
                    float2 o0 = make_float2(d[t][j][0] + bb.x, d[t][j][1] + bb.y);
                    float2 o1 = make_float2(d[t][j][2] + bb.x, d[t][j][3] + bb.y);
                    if (isWP) {
                        *(__half2*)(g_WPH + (size_t)row0 * DIM + col)       = __floats2half2_rn(o0.x, o0.y);
                        *(__half2*)(g_WPH + (size_t)(row0 + 8) * DIM + col) = __floats2half2_rn(o1.x, o1.y);
                    } else {
                        *(float2*)(g_WPO + (size_t)row0 * DIM + col)       = o0;
                        *(float2*)(g_WPO + (size_t)(row0 + 8) * DIM + col) = o1;
                    }
                }
        }
    }
#endif
}

#if USE_TC
// prefetch the gemm_b epilogue working set into L2 (224 worker threads, 2560 lines).
__device__ __forceinline__ void prefetch_epi(int t, int mb, int nh, int kp) {
    for (int i = t; i < 2560; i += 224) {
        const void* p;
        if (i < 1024) {                 // wq: 128 rows x 8 lines (256 fp32)
            int r = i >> 3, l = i & 7;
            p = g_WPO + (size_t)(mb * TILE_M + r) * DIM + nh * 256 + l * 32;
        } else if (i < 1536) {          // wph: 128 rows x 4 lines (256 fp16)
            int j = i - 1024; int r = j >> 2, l = j & 3;
            p = g_WPH + (size_t)(mb * TILE_M + r) * DIM + nh * 256 + l * 64;
        } else {                        // c: 2 branches x 128 rows x 4 lines
            int j = i - 1536; int kk = j >> 9, rem = j & 511, r = rem >> 2, l = rem & 3;
            p = g_C16 + ((size_t)(kp * 2 + kk) * B_ROWS + mb * TILE_M + r) * DIM + nh * 256 + l * 64;
        }
        PREFETCH_L2(p);
    }
}
#endif

// ---------------- Stage B: 2 branches x 256 cols per CTA ----------------
// grid (4 nh, 64 mb, 2 kp), 256 threads, 1 CTA/SM. 3 TMA stages of 64 KB.
__global__ void __launch_bounds__(256, 1)
gemm_b_kernel(float* __restrict__ out,
              const __grid_constant__ CUtensorMap tmaC,
              const __grid_constant__ CUtensorMap tmaW) {
    extern __shared__ char smem_raw[];
    uint32_t sb = (smem_u32(smem_raw) + 1023u) & ~1023u;
    const uint32_t buf = sb + HDR_BYTES;
    const int nh = blockIdx.x;          // 0..3 (256-col slice)
    const int mb = blockIdx.y;
    const int kp = blockIdx.z;          // branch pair: k = kp*2 + {0,1}
    const int tid = threadIdx.x;
    int wid = tid >> 5, lane = tid & 31;

#if USE_TC
    // barriers: full[0..2]@16..32, done[0..2]@40..56, fin@64
    if ((tid >> 5) == 0) { TCGEN05_ALLOC(sb, 512); TCGEN05_RELINQUISH(); }
    __syncthreads();
    uint32_t tmem;
    asm volatile("ld.shared.b32 %0, [%1];" : "=r"(tmem) : "r"(sb));
    if (tid == 0) {
#pragma unroll
        for (int p = 0; p < 3; ++p) { MBARRIER_INIT(sb + 16 + 8 * p, 1); MBARRIER_INIT(sb + 40 + 8 * p, 1); }
        MBARRIER_INIT(sb + 64, 1);
    }
    __syncthreads();

    if (tid == 0) {
        const int arow0 = (kp * 2 + 0) * B_ROWS + mb * TILE_M;
        const int arow1 = (kp * 2 + 1) * B_ROWS + mb * TILE_M;
        const int brow  = DIM + nh * 256;
        // prologue: 2 buffers in flight (3rd filled at iter 0 without waiting)
#pragma unroll
        for (int p = 0; p < 2; ++p) {
            uint32_t aB = buf + (uint32_t)p * STAGE_B;
            MBARRIER_EXPECT_TX(sb + 16 + 8 * p, 65536);
            TMA_LOAD_2D(aB,         &tmaC, p * KT, arow0, sb + 16 + 8 * p);
            TMA_LOAD_2D(aB + 16384, &tmaC, p * KT, arow1, sb + 16 + 8 * p);
            TMA_LOAD_2D(aB + 32768, &tmaW, p * KT, brow,  sb + 16 + 8 * p);
        }
#pragma unroll 1
        for (int i = 0; i < NCHUNKS; ++i) {
            int b = i % 3;
            int ph = (i / 3) & 1;
            uint32_t aB = buf + (uint32_t)b * STAGE_B;
            MBARRIER_WAIT_PARITY(sb + 16 + 8 * b, ph);
            uint64_t bd = MAKE_SMEM_DESC(aB + 32768);
#pragma unroll
            for (int kk = 0; kk < 2; ++kk) {
                uint64_t ad = MAKE_SMEM_DESC(aB + kk * 16384);
#pragma unroll
                for (int ks = 0; ks < 4; ++ks) {
                    uint32_t en = (i > 0 || ks > 0) ? 1u : 0u;
                    MMA_F16_SS(tmem + kk * 256, ad + ks * 2, bd + ks * 2, IDESC256, en);
                }
            }
            TCGEN05_COMMIT(sb + 40 + 8 * b);
            // refill chunk i+2 into buffer (i+2)%3 == (i-1)%3: gated on done(i-1), ~free
            if (i + 2 < NCHUNKS) {
                int j = i + 2, bb = j % 3;
                uint32_t jB = buf + (uint32_t)bb * STAGE_B;
                if (i >= 1) MBARRIER_WAIT_PARITY(sb + 40 + 8 * bb, ((i - 1) / 3) & 1);
                MBARRIER_EXPECT_TX(sb + 16 + 8 * bb, 65536);
                TMA_LOAD_2D(jB,         &tmaC, j * KT, arow0, sb + 16 + 8 * bb);
                TMA_LOAD_2D(jB + 16384, &tmaC, j * KT, arow1, sb + 16 + 8 * bb);
                TMA_LOAD_2D(jB + 32768, &tmaW, j * KT, brow,  sb + 16 + 8 * bb);
            }
        }
        TCGEN05_COMMIT(sb + 64);
    } else if (tid >= 32) {
        prefetch_epi(tid - 32, mb, nh, kp);
    }
    MBARRIER_WAIT_PARITY(sb + 64, 0);
    TCGEN05_FENCE_AFTER();

    // 8-warp fused epilogue: sub = row group; chc = column half of the 256-col slice.
    int sub = wid & 3, chc = wid >> 2;
    int row = mb * TILE_M + sub * 32 + lane;
    const int coff = nh * 256 + chc * 128;
    const __half* wp_row = g_WPH + (size_t)row * DIM + coff;
    const float*  wq_row = g_WPO + (size_t)row * DIM + coff;
    float score[2] = {0.f, 0.f};
#pragma unroll 1
    for (int c0 = 0; c0 < 128; c0 += 32) {
        float wq[32];
        __half2 wph[16];
#pragma unroll
        for (int q = 0; q < 8; ++q) *(float4*)(wq + q * 4) = *(const float4*)(wq_row + c0 + q * 4);
#pragma unroll
        for (int q = 0; q < 4; ++q) *(uint4*)(wph + q * 4) = *(const uint4*)(wp_row + c0 + q * 8);
#pragma unroll
        for (int kk = 0; kk < 2; ++kk) {
            uint32_t d[32];
            TCGEN05_LD_32X32B_X32(d, tmem + kk * 256 + chc * 128 + c0);
            TCGEN05_WAIT_LD();
            const __half* c_row = g_C16 + ((size_t)(kp * 2 + kk) * B_ROWS + row) * DIM + coff;
            float sk = 0.f;
#pragma unroll
            for (int jj = 0; jj < 8; ++jj) {
                float2 wp01 = __half22float2(wph[jj * 2]);
                float2 wp23 = __half22float2(wph[jj * 2 + 1]);
                uint2 cu = *(const uint2*)(c_row + c0 + jj * 4);
                float2 cv01 = __half22float2(*reinterpret_cast<__half2*>(&cu.x));
                float2 cv23 = __half22float2(*reinterpret_cast<__half2*>(&cu.y));
                float z, g;
                z = __uint_as_float(d[jj * 4 + 0]) + wp01.x;
                g = __fdividef(1.f, 1.f + __expf(-z)); sk += cv01.x * g * wq[jj * 4 + 0];
                z = __uint_as_float(d[jj * 4 + 1]) + wp01.y;
                g = __fdividef(1.f, 1.f + __expf(-z)); sk += cv01.y * g * wq[jj * 4 + 1];
                z = __uint_as_float(d[jj * 4 + 2]) + wp23.x;
                g = __fdividef(1.f, 1.f + __expf(-z)); sk += cv23.x * g * wq[jj * 4 + 2];
                z = __uint_as_float(d[jj * 4 + 3]) + wp23.y;
                g = __fdividef(1.f, 1.f + __expf(-z)); sk += cv23.y * g * wq[jj * 4 + 3];
            }
            score[kk] += sk;
        }
    }
    atomicAdd(out + (size_t)row * 4 + kp * 2 + 0, score[0]);
    atomicAdd(out + (size_t)row * 4 + kp * 2 + 1, score[1]);

    TCGEN05_FENCE_BEFORE();
    __syncthreads();
    if ((threadIdx.x >> 5) == 0) TCGEN05_DEALLOC(tmem, 512);
#else
    const __half* gA = g_C16 + (size_t)kp * 2 * CSTR + (size_t)mb * TILE_M * DIM;
    const __half* gB = g_W16 + (size_t)1 * DIM * DIM + (size_t)nh * 256 * DIM;
#pragma unroll 1
    for (int kk = 0; kk < 2; ++kk) {
#pragma unroll 1
        for (int ns = 0; ns < 2; ++ns) {
            float d[2][16][4] = {};
            fb_gemm(gA + (size_t)kk * CSTR, gB + (size_t)ns * 128 * DIM, buf, wid, lane, d);
            if (wid < 4) {
                float s[4] = {0.f, 0.f, 0.f, 0.f};
#pragma unroll
                for (int t = 0; t < 2; ++t)
#pragma unroll
                    for (int j = 0; j < 16; ++j) {
                        int col = nh * 256 + ns * 128 + j * 8 + (lane & 3) * 2;
#pragma unroll
                        for (int h = 0; h < 2; ++h) {
                            int row = mb * TILE_M + wid * 32 + t * 16 + (lane >> 2) + h * 8;
                            float2 wp = __half22float2(*(const __half2*)(g_WPH + (size_t)row * DIM + col));
                            float2 cv = __half22float2(*(const __half2*)(g_C16 + ((size_t)(kp * 2 + kk) * B_ROWS + row) * DIM + col));
                            float2 wq = *(const float2*)(g_WPO + (size_t)row * DIM + col);
                            float z, g;
                            z = d[t][j][h * 2 + 0] + wp.x;
                            g = __fdividef(1.f, 1.f + __expf(-z)); s[t * 2 + h] += cv.x * g * wq.x;
                            z = d[t][j][h * 2 + 1] + wp.y;
                            g = __fdividef(1.f, 1.f + __expf(-z)); s[t * 2 + h] += cv.y * g * wq.y;
                        }
                    }
#pragma unroll
                for (int i = 0; i < 4; ++i) {
                    s[i] += __shfl_xor_sync(0xffffffff, s[i], 1);
                    s[i] += __shfl_xor_sync(0xffffffff, s[i], 2);
                }
                if ((lane & 3) == 0) {
#pragma unroll
                    for (int t = 0; t < 2; ++t)
#pragma unroll
                        for (int h = 0; h < 2; ++h) {
                            int row = mb * TILE_M + wid * 32 + t * 16 + (lane >> 2) + h * 8;
                            atomicAdd(out + (size_t)row * 4 + kp * 2 + kk, s[t * 2 + h]);
                        }
                }
            }
            __syncthreads();
        }
    }
#endif
}

// ---------------- host: tensormap construction ----------------
typedef CUresult (*PFN_encodeTiled)(
    CUtensorMap*, CUtensorMapDataType, cuuint32_t, void*,
    const cuuint64_t*, const cuuint64_t*, const cuuint32_t*, const cuuint32_t*,
    CUtensorMapInterleave, CUtensorMapSwizzle, CUtensorMapL2promotion, CUtensorMapFloatOOBfill);

static void make_map(PFN_encodeTiled enc, CUtensorMap* m, void* base,
                     unsigned long long rows, unsigned box_rows) {
    cuuint64_t dims[2]    = {(cuuint64_t)DIM, (cuuint64_t)rows};
    cuuint64_t strides[1] = {(cuuint64_t)DIM * 2};
    cuuint32_t box[2]     = {(cuuint32_t)KT, (cuuint32_t)box_rows};
    cuuint32_t es[2]      = {1, 1};
    enc(m, CU_TENSOR_MAP_DATA_TYPE_UINT16, 2, base, dims, strides, box, es,
        CU_TENSOR_MAP_INTERLEAVE_NONE, CU_TENSOR_MAP_SWIZZLE_128B,
        CU_TENSOR_MAP_L2_PROMOTION_L2_128B, CU_TENSOR_MAP_FLOAT_OOB_FILL_NONE);
}

extern "C" void kernel_launch(void* const* d_in, const int* in_sizes, int n_in,
                              void* d_out, int out_size) {
    const float* P   = (const float*)d_in[0];
    const float* C1  = (const float*)d_in[1];
    const float* C2  = (const float*)d_in[2];
    const float* C3  = (const float*)d_in[3];
    const float* C4  = (const float*)d_in[4];
    const float* GWP = (const float*)d_in[5];
    const float* GWC = (const float*)d_in[6];
    const float* GB  = (const float*)d_in[7];
    const float* OW  = (const float*)d_in[8];
    const float* OB  = (const float*)d_in[9];
    float* out = (float*)d_out;

    cudaFuncSetAttribute(gemm_a_kernel, cudaFuncAttributeMaxDynamicSharedMemorySize, SMEM_DYN);
    cudaFuncSetAttribute(gemm_b_kernel, cudaFuncAttributeMaxDynamicSharedMemorySize, SMEM_DYN);

    PFN_encodeTiled enc = nullptr;
    cudaDriverEntryPointQueryResult qres;
    cudaGetDriverEntryPoint("cuTensorMapEncodeTiled", (void**)&enc, cudaEnableDefault, &qres);
    void *pP = nullptr, *pC = nullptr, *pW = nullptr;
    cudaGetSymbolAddress(&pP, g_P16);
    cudaGetSymbolAddress(&pC, g_C16);
    cudaGetSymbolAddress(&pW, g_W16);
    CUtensorMap tmaP, tmaC, tmaW256;
    make_map(enc, &tmaP,    pP, (unsigned long long)B_ROWS,      128);
    make_map(enc, &tmaC,    pC, (unsigned long long)B_ROWS * 4,  128);
    make_map(enc, &tmaW256, pW, (unsigned long long)DIM * 3,     256);

    convert_p_kernel<<<B_ROWS * DIM / 4 / 256, 256>>>(P, out);
    convert_w_kernel<<<dim3(DIM / 32, DIM / 32, 3), dim3(32, 8)>>>(GWP, GWC, OW);
    gemm_a_kernel<<<dim3(8, B_ROWS / TILE_M), 256, SMEM_DYN>>>(GB, OB, C1, C2, C3, C4, tmaP, tmaW256);
    gemm_b_kernel<<<dim3(4, B_ROWS / TILE_M, 2), 256, SMEM_DYN>>>(out, tmaC, tmaW256);
}